// round 4
// baseline (speedup 1.0000x reference)
#include <cuda_runtime.h>
#include <cstdint>

#define NN 100000
#define NE 1600000
#define NG 1024
#define HID 128
#define BN_EPS 1e-5f

// ---------------- device scratch ----------------
__device__ int   d_deg[NN];
__device__ int   d_rowstart[NN + 1];
__device__ int   d_cursor[NN];
__device__ int   d_csr_src[NE];
#define SCAN_B 512
#define NSB ((NN + SCAN_B - 1) / SCAN_B)
__device__ int   d_blocksums[NSB];
__device__ int   d_blockoff[NSB];
__device__ float d_z7[NN * 8];
__device__ float d_A[NN * HID];
__device__ float d_z[NN * HID];      // also reused: first NN*8 = padded x8
__device__ float d_xs[NN * 3 * HID];
__device__ float d_g[NG * 3 * HID];
__device__ int   d_gstart[NG + 1];
// W fragment tables: [5 layers][2 nwarp][16 kt][4 g][32 lane][4 floats]
__device__ float d_wf[5 * 2 * 16 * 4 * 32 * 4];

// ---------------- CSR build ----------------
__global__ void k_zero_deg() {
    int i = blockIdx.x * blockDim.x + threadIdx.x;
    if (i < NN) d_deg[i] = 0;
}

__global__ void k_hist(const int* __restrict__ ei) {
    int e = blockIdx.x * blockDim.x + threadIdx.x;
    if (e < NE) atomicAdd(&d_deg[ei[NE + e]], 1);
}

__global__ void k_scan1() {
    __shared__ int s[SCAN_B];
    int t = threadIdx.x;
    int i = blockIdx.x * SCAN_B + t;
    int v = (i < NN) ? d_deg[i] : 0;
    s[t] = v;
    __syncthreads();
    for (int off = 1; off < SCAN_B; off <<= 1) {
        int x = (t >= off) ? s[t - off] : 0;
        __syncthreads();
        s[t] += x;
        __syncthreads();
    }
    if (i < NN) d_rowstart[i] = s[t];
    if (t == SCAN_B - 1) d_blocksums[blockIdx.x] = s[t];
}

__global__ void k_scan2() {
    __shared__ int s[256];
    int t = threadIdx.x;
    int v = (t < NSB) ? d_blocksums[t] : 0;
    s[t] = v;
    __syncthreads();
    for (int off = 1; off < 256; off <<= 1) {
        int x = (t >= off) ? s[t - off] : 0;
        __syncthreads();
        s[t] += x;
        __syncthreads();
    }
    if (t < NSB) d_blockoff[t] = s[t] - v;
}

__global__ void k_scan3() {
    int i = blockIdx.x * blockDim.x + threadIdx.x;
    if (i < NN) {
        int incl = d_rowstart[i];
        int ex = incl - d_deg[i] + d_blockoff[i >> 9];
        d_rowstart[i] = ex;
        d_cursor[i] = ex;
    }
    if (i == 0) d_rowstart[NN] = NE;
}

__global__ void k_fill(const int* __restrict__ ei) {
    int e = blockIdx.x * blockDim.x + threadIdx.x;
    if (e < NE) {
        int dst = ei[NE + e];
        int pos = atomicAdd(&d_cursor[dst], 1);
        d_csr_src[pos] = ei[e];
    }
}

// ---------------- layer 0 ----------------
// pad x [NN,7] -> x8 [NN,8] stored in d_z
__global__ void k_pad8(const float* __restrict__ x) {
    int gt = blockIdx.x * blockDim.x + threadIdx.x;
    if (gt >= NN * 8) return;
    int n = gt >> 3, j = gt & 7;
    d_z[gt] = (j < 7) ? x[n * 7 + j] : 0.0f;
}

// z7 = x8 + sum_{src} x8[src]; 8 lanes per node
__global__ void k_agg8() {
    int gt = blockIdx.x * blockDim.x + threadIdx.x;
    if (gt >= NN * 8) return;
    int n = gt >> 3, j = gt & 7;
    float a = d_z[n * 8 + j];
    int s = d_rowstart[n], e = d_rowstart[n + 1];
    for (int i = s; i < e; i++) {
        int src = d_csr_src[i];
        a += __ldg(d_z + src * 8 + j);
    }
    d_z7[n * 8 + j] = a;
}

// lin0: A = relu(z7 @ w1_0 + b1_0), w1_0 is [7][128]
__global__ void k_lin0(const float* __restrict__ w1, const float* __restrict__ b1) {
    __shared__ float ws[7 * 128 + 128];
    int tid = threadIdx.x;
    for (int i = tid; i < 7 * 128 + 128; i += 256)
        ws[i] = (i < 7 * 128) ? w1[i] : b1[i - 7 * 128];
    __syncthreads();
    int gt = blockIdx.x * 256 + tid;
    int node = gt >> 5;
    int cg = gt & 31;
    if (node >= NN) return;
    float a[7];
#pragma unroll
    for (int j = 0; j < 7; j++) a[j] = d_z7[node * 8 + j];
    const float* bb = ws + 7 * 128;
    float4 acc = *(const float4*)(bb + cg * 4);
#pragma unroll
    for (int j = 0; j < 7; j++) {
        float4 w = *(const float4*)(ws + j * 128 + cg * 4);
        acc.x += a[j] * w.x;
        acc.y += a[j] * w.y;
        acc.z += a[j] * w.z;
        acc.w += a[j] * w.w;
    }
    acc.x = fmaxf(acc.x, 0.f); acc.y = fmaxf(acc.y, 0.f);
    acc.z = fmaxf(acc.z, 0.f); acc.w = fmaxf(acc.w, 0.f);
    *(float4*)(d_A + node * HID + cg * 4) = acc;
}

// ---------------- 128-dim aggregation ----------------
__global__ void k_agg128(const float* __restrict__ h, int ldh) {
    int gt = blockIdx.x * blockDim.x + threadIdx.x;
    int n = gt >> 5;
    int lane = gt & 31;
    if (n >= NN) return;
    float4 acc = *(const float4*)(h + (size_t)n * ldh + lane * 4);
    int s = d_rowstart[n], e = d_rowstart[n + 1];
    int i = s;
    for (; i + 1 < e; i += 2) {
        int s0 = d_csr_src[i];
        int s1 = d_csr_src[i + 1];
        float4 v0 = *(const float4*)(h + (size_t)s0 * ldh + lane * 4);
        float4 v1 = *(const float4*)(h + (size_t)s1 * ldh + lane * 4);
        acc.x += v0.x; acc.y += v0.y; acc.z += v0.z; acc.w += v0.w;
        acc.x += v1.x; acc.y += v1.y; acc.z += v1.z; acc.w += v1.w;
    }
    if (i < e) {
        int s0 = d_csr_src[i];
        float4 v0 = *(const float4*)(h + (size_t)s0 * ldh + lane * 4);
        acc.x += v0.x; acc.y += v0.y; acc.z += v0.z; acc.w += v0.w;
    }
    *(float4*)(d_z + n * HID + lane * 4) = acc;
}

// ---------------- tf32 helpers ----------------
__device__ __forceinline__ float tf32r(float x) {
    asm("cvt.rna.tf32.f32 %0, %0;" : "+f"(x));
    return x;
}

// ---------------- W fragment precompute ----------------
// d_wf layout: [layer][nw][kt][g][lane][4]; j = g*4+s; ni=j>>1; b=j&1
// value = W[kt*8 + c + 4b][nw*64 + ni*8 + r], r=lane>>2, c=lane&3
__global__ void k_wfrag(const float* __restrict__ w0, const float* __restrict__ w1,
                        const float* __restrict__ w2, const float* __restrict__ w3,
                        const float* __restrict__ w4) {
    int idx = blockIdx.x * blockDim.x + threadIdx.x;
    if (idx >= 5 * 16384) return;
    int s = idx & 3;
    int lane = (idx >> 2) & 31;
    int g = (idx >> 7) & 3;
    int kt = (idx >> 9) & 15;
    int nw = (idx >> 13) & 1;
    int layer = idx >> 14;
    int j = g * 4 + s;
    int ni = j >> 1, b = j & 1;
    int r = lane >> 2, c = lane & 3;
    int k = kt * 8 + c + 4 * b;
    int n = nw * 64 + ni * 8 + r;
    const float* W = (layer == 0) ? w0 : (layer == 1) ? w1 : (layer == 2) ? w2
                   : (layer == 3) ? w3 : w4;
    d_wf[idx] = tf32r(__ldg(W + k * 128 + n));
}

// ---------------- tf32 tensor-core GEMM, fragment-order operands ----------------
// C[M,128] = relu(A[M,128] @ W + bias). BM=128. 8 warps = 4m x 2n, warp: 32x64.
// A staged in smem in fragment order: af[mw][kt(pad 260)][mi*128][lane*4 + s]
#define AF_FLOATS (4 * 16 * 260)          // 16640
#define GEMM_SMEM (AF_FLOATS * 4)         // 66560 B

#define MMA_TF32(ac, a0, a1, a2, a3, b0, b1)                                   \
    asm volatile(                                                              \
        "mma.sync.aligned.m16n8k8.row.col.f32.tf32.tf32.f32 "                  \
        "{%0,%1,%2,%3}, {%4,%5,%6,%7}, {%8,%9}, {%0,%1,%2,%3};"                \
        : "+f"(ac[0]), "+f"(ac[1]), "+f"(ac[2]), "+f"(ac[3])                   \
        : "r"(a0), "r"(a1), "r"(a2), "r"(a3), "r"(b0), "r"(b1))

__global__ void __launch_bounds__(256, 2)
k_gemm_tc(const float* __restrict__ A, int lda,
          const float* __restrict__ wfrag, const float* __restrict__ bias,
          float* __restrict__ C, int ldc, int M) {
    extern __shared__ float af[];
    int tid = threadIdx.x;
    int m0 = blockIdx.x * 128;

    // stage A tile into fragment-order smem
#pragma unroll
    for (int it = tid; it < 128 * 32; it += 256) {
        int row = it >> 5, q = it & 31;
        int m = m0 + row;
        float4 v = make_float4(0.f, 0.f, 0.f, 0.f);
        if (m < M) v = *(const float4*)(A + (size_t)m * lda + q * 4);
        int mw = row >> 5, mr = row & 31;
        int mi = mr >> 4, rr = mr & 15;
        int rowslot = rr >> 3, r = rr & 7;
        int kt = q >> 1, hi = q & 1;
        float* p = af + mw * 4160 + kt * 260 + mi * 128 + r * 16 + hi * 2 + rowslot;
        p[0]  = tf32r(v.x);   // c=0
        p[4]  = tf32r(v.y);   // c=1
        p[8]  = tf32r(v.z);   // c=2
        p[12] = tf32r(v.w);   // c=3
    }
    __syncthreads();

    int lane = tid & 31;
    int warp = tid >> 5;
    int mw = warp >> 1;          // 0..3
    int nw = warp & 1;           // 0..1
    int wm = mw * 32, wn = nw * 64;
    int r = lane >> 2, c = lane & 3;

    const uint4* wfv = (const uint4*)(wfrag + nw * 8192);
    const float* amy = af + mw * 4160 + lane * 4;

    float acc[2][8][4];
#pragma unroll
    for (int mi = 0; mi < 2; mi++)
#pragma unroll
        for (int ni = 0; ni < 8; ni++)
#pragma unroll
            for (int j = 0; j < 4; j++) acc[mi][ni][j] = 0.f;

    uint4 bf[4];
#pragma unroll
    for (int g = 0; g < 4; g++) bf[g] = wfv[g * 32 + lane];

#pragma unroll
    for (int kt = 0; kt < 16; kt++) {
        uint4 bn[4];
        if (kt < 15) {
#pragma unroll
            for (int g = 0; g < 4; g++) bn[g] = wfv[((kt + 1) * 4 + g) * 32 + lane];
        }
        uint4 a0 = *(const uint4*)(amy + kt * 260);
        uint4 a1 = *(const uint4*)(amy + kt * 260 + 128);
        // ni even: (x,y) of bf[ni>>1]; odd: (z,w)
        MMA_TF32(acc[0][0], a0.x, a0.y, a0.z, a0.w, bf[0].x, bf[0].y);
        MMA_TF32(acc[1][0], a1.x, a1.y, a1.z, a1.w, bf[0].x, bf[0].y);
        MMA_TF32(acc[0][1], a0.x, a0.y, a0.z, a0.w, bf[0].z, bf[0].w);
        MMA_TF32(acc[1][1], a1.x, a1.y, a1.z, a1.w, bf[0].z, bf[0].w);
        MMA_TF32(acc[0][2], a0.x, a0.y, a0.z, a0.w, bf[1].x, bf[1].y);
        MMA_TF32(acc[1][2], a1.x, a1.y, a1.z, a1.w, bf[1].x, bf[1].y);
        MMA_TF32(acc[0][3], a0.x, a0.y, a0.z, a0.w, bf[1].z, bf[1].w);
        MMA_TF32(acc[1][3], a1.x, a1.y, a1.z, a1.w, bf[1].z, bf[1].w);
        MMA_TF32(acc[0][4], a0.x, a0.y, a0.z, a0.w, bf[2].x, bf[2].y);
        MMA_TF32(acc[1][4], a1.x, a1.y, a1.z, a1.w, bf[2].x, bf[2].y);
        MMA_TF32(acc[0][5], a0.x, a0.y, a0.z, a0.w, bf[2].z, bf[2].w);
        MMA_TF32(acc[1][5], a1.x, a1.y, a1.z, a1.w, bf[2].z, bf[2].w);
        MMA_TF32(acc[0][6], a0.x, a0.y, a0.z, a0.w, bf[3].x, bf[3].y);
        MMA_TF32(acc[1][6], a1.x, a1.y, a1.z, a1.w, bf[3].x, bf[3].y);
        MMA_TF32(acc[0][7], a0.x, a0.y, a0.z, a0.w, bf[3].z, bf[3].w);
        MMA_TF32(acc[1][7], a1.x, a1.y, a1.z, a1.w, bf[3].z, bf[3].w);
        if (kt < 15) {
#pragma unroll
            for (int g = 0; g < 4; g++) bf[g] = bn[g];
        }
    }

    // epilogue: bias + relu
#pragma unroll
    for (int mi = 0; mi < 2; mi++) {
        int row0 = m0 + wm + mi * 16 + r;
#pragma unroll
        for (int ni = 0; ni < 8; ni++) {
            int col = wn + ni * 8 + c * 2;
            float bx = __ldg(bias + col);
            float by = __ldg(bias + col + 1);
            if (row0 < M) {
                float2 o;
                o.x = fmaxf(acc[mi][ni][0] + bx, 0.f);
                o.y = fmaxf(acc[mi][ni][1] + by, 0.f);
                *(float2*)(C + (size_t)row0 * ldc + col) = o;
            }
            int row1 = row0 + 8;
            if (row1 < M) {
                float2 o;
                o.x = fmaxf(acc[mi][ni][2] + bx, 0.f);
                o.y = fmaxf(acc[mi][ni][3] + by, 0.f);
                *(float2*)(C + (size_t)row1 * ldc + col) = o;
            }
        }
    }
}

// ---------------- pooling ----------------
__global__ void k_bounds(const int* __restrict__ batch) {
    int i = blockIdx.x * blockDim.x + threadIdx.x;
    if (i >= NN) return;
    int b = batch[i];
    int pb = (i == 0) ? -1 : batch[i - 1];
    for (int g = pb + 1; g <= b; g++) d_gstart[g] = i;
    if (i == NN - 1)
        for (int g = b + 1; g <= NG; g++) d_gstart[g] = NN;
}

__global__ void k_pool() {
    int g = blockIdx.x;
    int t = threadIdx.x;
    int s = d_gstart[g], e = d_gstart[g + 1];
    float a0 = 0.f, a1 = 0.f, a2 = 0.f;
    for (int n = s; n < e; n++) {
        const float* row = d_xs + (size_t)n * 384;
        a0 += row[t];
        a1 += row[128 + t];
        a2 += row[256 + t];
    }
    d_g[g * 384 + t] = a0;
    d_g[g * 384 + 128 + t] = a1;
    d_g[g * 384 + 256 + t] = a2;
}

// ---------------- classifier ----------------
__global__ void __launch_bounds__(256)
k_clf(const float* __restrict__ w1, const float* __restrict__ b1,
      const float* __restrict__ w2, const float* __restrict__ b2,
      const float* __restrict__ gamma, const float* __restrict__ beta,
      const float* __restrict__ mean, const float* __restrict__ var,
      float* __restrict__ out) {
    __shared__ float sg[16 * 384];
    __shared__ float sz[16 * 256];
    int tid = threadIdx.x;
    int g0 = blockIdx.x * 16;
    for (int i = tid; i < 16 * 384; i += 256) sg[i] = d_g[g0 * 384 + i];
    __syncthreads();
    float acc[16];
#pragma unroll
    for (int gi = 0; gi < 16; gi++) acc[gi] = 0.f;
    for (int k = 0; k < 384; k++) {
        float w = __ldg(w1 + k * 256 + tid);
#pragma unroll
        for (int gi = 0; gi < 16; gi++) acc[gi] += sg[gi * 384 + k] * w;
    }
    float bb = __ldg(b1 + tid);
    float mu = __ldg(mean + tid);
    float iv = rsqrtf(__ldg(var + tid) + BN_EPS);
    float ga = __ldg(gamma + tid);
    float be = __ldg(beta + tid);
#pragma unroll
    for (int gi = 0; gi < 16; gi++) {
        float zv = acc[gi] + bb;
        zv = (zv - mu) * iv * ga + be;
        sz[gi * 256 + tid] = fmaxf(zv, 0.f);
    }
    __syncthreads();
    if (tid < 32) {
        int gi = tid >> 1, c = tid & 1;
        float s = __ldg(b2 + c);
        for (int k = 0; k < 256; k++) s += sz[gi * 256 + k] * __ldg(w2 + k * 2 + c);
        out[(g0 + gi) * 2 + c] = s;
    }
}

// ---------------- launch ----------------
extern "C" void kernel_launch(void* const* d_in, const int* in_sizes, int n_in,
                              void* d_out, int out_size) {
    const float* x   = (const float*)d_in[0];
    const int*   ei  = (const int*)d_in[1];
    const int*   bat = (const int*)d_in[2];
    const float* w1_0 = (const float*)d_in[3];
    const float* b1_0 = (const float*)d_in[4];
    const float* w2_0 = (const float*)d_in[5];
    const float* b2_0 = (const float*)d_in[6];
    const float* w1_1 = (const float*)d_in[7];
    const float* b1_1 = (const float*)d_in[8];
    const float* w2_1 = (const float*)d_in[9];
    const float* b2_1 = (const float*)d_in[10];
    const float* w1_2 = (const float*)d_in[11];
    const float* b1_2 = (const float*)d_in[12];
    const float* w2_2 = (const float*)d_in[13];
    const float* b2_2 = (const float*)d_in[14];
    const float* cw1 = (const float*)d_in[15];
    const float* cb1 = (const float*)d_in[16];
    const float* cw2 = (const float*)d_in[17];
    const float* cb2 = (const float*)d_in[18];
    const float* bng = (const float*)d_in[19];
    const float* bnb = (const float*)d_in[20];
    const float* bnm = (const float*)d_in[21];
    const float* bnv = (const float*)d_in[22];
    float* out = (float*)d_out;

    cudaFuncSetAttribute(k_gemm_tc, cudaFuncAttributeMaxDynamicSharedMemorySize,
                         GEMM_SMEM);

    static float* p_xs = nullptr;
    static float* p_A = nullptr;
    static float* p_z = nullptr;
    static float* p_wf = nullptr;
    if (!p_xs) {
        void* tmp;
        cudaGetSymbolAddress(&tmp, d_xs); p_xs = (float*)tmp;
        cudaGetSymbolAddress(&tmp, d_A);  p_A = (float*)tmp;
        cudaGetSymbolAddress(&tmp, d_z);  p_z = (float*)tmp;
        cudaGetSymbolAddress(&tmp, d_wf); p_wf = (float*)tmp;
    }

    int tb = 256;
    // W fragment tables (5 weight matrices used by the 5 tensor GEMMs)
    k_wfrag<<<(5 * 16384 + tb - 1) / tb, tb>>>(w2_0, w1_1, w2_1, w1_2, w2_2);
    // CSR build
    k_zero_deg<<<(NN + tb - 1) / tb, tb>>>();
    k_hist<<<(NE + tb - 1) / tb, tb>>>(ei);
    k_scan1<<<NSB, SCAN_B>>>();
    k_scan2<<<1, 256>>>();
    k_scan3<<<(NN + tb - 1) / tb, tb>>>();
    k_fill<<<(NE + tb - 1) / tb, tb>>>(ei);

    int gemm_grid = (NN + 127) / 128;
    int agg_grid = (NN * 32 + tb - 1) / tb;
    int g8 = (NN * 8 + tb - 1) / tb;

    // layer 0
    k_pad8<<<g8, tb>>>(x);
    k_agg8<<<g8, tb>>>();
    k_lin0<<<agg_grid, tb>>>(w1_0, b1_0);
    k_gemm_tc<<<gemm_grid, tb, GEMM_SMEM>>>(p_A, HID, p_wf + 0 * 16384, b2_0, p_xs + 0, 384, NN);
    // layer 1
    k_agg128<<<agg_grid, tb>>>(p_xs + 0, 384);
    k_gemm_tc<<<gemm_grid, tb, GEMM_SMEM>>>(p_z, HID, p_wf + 1 * 16384, b1_1, p_A, HID, NN);
    k_gemm_tc<<<gemm_grid, tb, GEMM_SMEM>>>(p_A, HID, p_wf + 2 * 16384, b2_1, p_xs + 128, 384, NN);
    // layer 2
    k_agg128<<<agg_grid, tb>>>(p_xs + 128, 384);
    k_gemm_tc<<<gemm_grid, tb, GEMM_SMEM>>>(p_z, HID, p_wf + 3 * 16384, b1_2, p_A, HID, NN);
    k_gemm_tc<<<gemm_grid, tb, GEMM_SMEM>>>(p_A, HID, p_wf + 4 * 16384, b2_2, p_xs + 256, 384, NN);
    // pool + classifier
    k_bounds<<<(NN + tb - 1) / tb, tb>>>(bat);
    k_pool<<<NG, 128>>>();
    k_clf<<<NG / 16, 256>>>(cw1, cb1, cw2, cb2, bng, bnb, bnm, bnv, out);
}

// round 8
// speedup vs baseline: 1.3287x; 1.3287x over previous
#include <cuda_runtime.h>
#include <cstdint>

#define NN 100000
#define NE 1600000
#define NG 1024
#define HID 128
#define BN_EPS 1e-5f

// ---------------- device scratch ----------------
__device__ int   d_deg[NN];
__device__ int   d_rowstart[NN + 1];
__device__ int   d_cursor[NN];
__device__ int   d_csr_src[NE];
#define SCAN_B 512
#define NSB ((NN + SCAN_B - 1) / SCAN_B)
__device__ int   d_blocksums[NSB];
__device__ int   d_blockoff[NSB];
__device__ float d_z7[NN * 8];
__device__ float d_A[NN * HID];
__device__ float d_z[NN * HID];      // also reused: first NN*8 = padded x8
__device__ float d_xs[NN * 3 * HID];
__device__ float d_g[NG * 3 * HID];
__device__ int   d_gstart[NG + 1];
// W fragment tables: [5 layers][2 nwarp][16 kt][4 g][32 lane][4 floats]
__device__ float d_wf[5 * 2 * 16 * 4 * 32 * 4];

// ---------------- CSR build ----------------
__global__ void k_zero_deg() {
    int i = blockIdx.x * blockDim.x + threadIdx.x;
    if (i < NN) d_deg[i] = 0;
}

__global__ void k_hist(const int* __restrict__ ei) {
    int e = blockIdx.x * blockDim.x + threadIdx.x;
    if (e < NE) atomicAdd(&d_deg[ei[NE + e]], 1);
}

__global__ void k_scan1() {
    __shared__ int s[SCAN_B];
    int t = threadIdx.x;
    int i = blockIdx.x * SCAN_B + t;
    int v = (i < NN) ? d_deg[i] : 0;
    s[t] = v;
    __syncthreads();
    for (int off = 1; off < SCAN_B; off <<= 1) {
        int x = (t >= off) ? s[t - off] : 0;
        __syncthreads();
        s[t] += x;
        __syncthreads();
    }
    if (i < NN) d_rowstart[i] = s[t];
    if (t == SCAN_B - 1) d_blocksums[blockIdx.x] = s[t];
}

__global__ void k_scan2() {
    __shared__ int s[256];
    int t = threadIdx.x;
    int v = (t < NSB) ? d_blocksums[t] : 0;
    s[t] = v;
    __syncthreads();
    for (int off = 1; off < 256; off <<= 1) {
        int x = (t >= off) ? s[t - off] : 0;
        __syncthreads();
        s[t] += x;
        __syncthreads();
    }
    if (t < NSB) d_blockoff[t] = s[t] - v;
}

__global__ void k_scan3() {
    int i = blockIdx.x * blockDim.x + threadIdx.x;
    if (i < NN) {
        int incl = d_rowstart[i];
        int ex = incl - d_deg[i] + d_blockoff[i >> 9];
        d_rowstart[i] = ex;
        d_cursor[i] = ex;
    }
    if (i == 0) d_rowstart[NN] = NE;
}

__global__ void k_fill(const int* __restrict__ ei) {
    int e = blockIdx.x * blockDim.x + threadIdx.x;
    if (e < NE) {
        int dst = ei[NE + e];
        int pos = atomicAdd(&d_cursor[dst], 1);
        d_csr_src[pos] = ei[e];
    }
}

// ---------------- layer 0 ----------------
// pad x [NN,7] -> x8 [NN,8] stored in d_z
__global__ void k_pad8(const float* __restrict__ x) {
    int gt = blockIdx.x * blockDim.x + threadIdx.x;
    if (gt >= NN * 8) return;
    int n = gt >> 3, j = gt & 7;
    d_z[gt] = (j < 7) ? x[n * 7 + j] : 0.0f;
}

// z7 = x8 + sum_{src} x8[src]; 8 lanes per node
__global__ void k_agg8() {
    int gt = blockIdx.x * blockDim.x + threadIdx.x;
    if (gt >= NN * 8) return;
    int n = gt >> 3, j = gt & 7;
    float a = d_z[n * 8 + j];
    int s = d_rowstart[n], e = d_rowstart[n + 1];
    for (int i = s; i < e; i++) {
        int src = d_csr_src[i];
        a += __ldg(d_z + src * 8 + j);
    }
    d_z7[n * 8 + j] = a;
}

// lin0: A = relu(z7 @ w1_0 + b1_0), w1_0 is [7][128]
__global__ void k_lin0(const float* __restrict__ w1, const float* __restrict__ b1) {
    __shared__ float ws[7 * 128 + 128];
    int tid = threadIdx.x;
    for (int i = tid; i < 7 * 128 + 128; i += 256)
        ws[i] = (i < 7 * 128) ? w1[i] : b1[i - 7 * 128];
    __syncthreads();
    int gt = blockIdx.x * 256 + tid;
    int node = gt >> 5;
    int cg = gt & 31;
    if (node >= NN) return;
    float a[7];
#pragma unroll
    for (int j = 0; j < 7; j++) a[j] = d_z7[node * 8 + j];
    const float* bb = ws + 7 * 128;
    float4 acc = *(const float4*)(bb + cg * 4);
#pragma unroll
    for (int j = 0; j < 7; j++) {
        float4 w = *(const float4*)(ws + j * 128 + cg * 4);
        acc.x += a[j] * w.x;
        acc.y += a[j] * w.y;
        acc.z += a[j] * w.z;
        acc.w += a[j] * w.w;
    }
    acc.x = fmaxf(acc.x, 0.f); acc.y = fmaxf(acc.y, 0.f);
    acc.z = fmaxf(acc.z, 0.f); acc.w = fmaxf(acc.w, 0.f);
    *(float4*)(d_A + node * HID + cg * 4) = acc;
}

// ---------------- 128-dim aggregation ----------------
__global__ void k_agg128(const float* __restrict__ h, int ldh) {
    int gt = blockIdx.x * blockDim.x + threadIdx.x;
    int n = gt >> 5;
    int lane = gt & 31;
    if (n >= NN) return;
    float4 acc = *(const float4*)(h + (size_t)n * ldh + lane * 4);
    int s = d_rowstart[n], e = d_rowstart[n + 1];
    int i = s;
    for (; i + 1 < e; i += 2) {
        int s0 = d_csr_src[i];
        int s1 = d_csr_src[i + 1];
        float4 v0 = *(const float4*)(h + (size_t)s0 * ldh + lane * 4);
        float4 v1 = *(const float4*)(h + (size_t)s1 * ldh + lane * 4);
        acc.x += v0.x; acc.y += v0.y; acc.z += v0.z; acc.w += v0.w;
        acc.x += v1.x; acc.y += v1.y; acc.z += v1.z; acc.w += v1.w;
    }
    if (i < e) {
        int s0 = d_csr_src[i];
        float4 v0 = *(const float4*)(h + (size_t)s0 * ldh + lane * 4);
        acc.x += v0.x; acc.y += v0.y; acc.z += v0.z; acc.w += v0.w;
    }
    *(float4*)(d_z + n * HID + lane * 4) = acc;
}

// ---------------- tf32 helpers ----------------
__device__ __forceinline__ float tf32r(float x) {
    asm("cvt.rna.tf32.f32 %0, %0;" : "+f"(x));
    return x;
}

// ---------------- W fragment precompute ----------------
// d_wf layout: [layer][nw][kt][g][lane][4]; j = g*4+s; ni=j>>1; b=j&1
// value = W[kt*8 + c + 4b][nw*64 + ni*8 + r], r=lane>>2, c=lane&3
__global__ void k_wfrag(const float* __restrict__ w0, const float* __restrict__ w1,
                        const float* __restrict__ w2, const float* __restrict__ w3,
                        const float* __restrict__ w4) {
    int idx = blockIdx.x * blockDim.x + threadIdx.x;
    if (idx >= 5 * 16384) return;
    int s = idx & 3;
    int lane = (idx >> 2) & 31;
    int g = (idx >> 7) & 3;
    int kt = (idx >> 9) & 15;
    int nw = (idx >> 13) & 1;
    int layer = idx >> 14;
    int j = g * 4 + s;
    int ni = j >> 1, b = j & 1;
    int r = lane >> 2, c = lane & 3;
    int k = kt * 8 + c + 4 * b;
    int n = nw * 64 + ni * 8 + r;
    const float* W = (layer == 0) ? w0 : (layer == 1) ? w1 : (layer == 2) ? w2
                   : (layer == 3) ? w3 : w4;
    d_wf[idx] = tf32r(__ldg(W + k * 128 + n));
}

// ---------------- tf32 tensor-core GEMM, fragment-order operands ----------------
// C[M,128] = relu(A[M,128] @ W + bias). BM=128. 8 warps = 4m x 2n, warp: 32x64.
// A staged in smem in fragment order: af[mw][kt(pad 260)][mi*128][lane*4 + t]
#define AF_FLOATS (4 * 16 * 260)          // 16640
#define GEMM_SMEM (AF_FLOATS * 4)         // 66560 B

#define MMA_TF32(ac, a0, a1, a2, a3, b0, b1)                                   \
    asm volatile(                                                              \
        "mma.sync.aligned.m16n8k8.row.col.f32.tf32.tf32.f32 "                  \
        "{%0,%1,%2,%3}, {%4,%5,%6,%7}, {%8,%9}, {%0,%1,%2,%3};"                \
        : "+f"(ac[0]), "+f"(ac[1]), "+f"(ac[2]), "+f"(ac[3])                   \
        : "r"(a0), "r"(a1), "r"(a2), "r"(a3), "r"(b0), "r"(b1))

__global__ void __launch_bounds__(256, 2)
k_gemm_tc(const float* __restrict__ A, int lda,
          const float* __restrict__ wfrag, const float* __restrict__ bias,
          float* __restrict__ C, int ldc, int M) {
    extern __shared__ float af[];
    int tid = threadIdx.x;
    int m0 = blockIdx.x * 128;

    // stage A tile into fragment-order smem
#pragma unroll
    for (int it = tid; it < 128 * 32; it += 256) {
        int row = it >> 5, q = it & 31;
        int m = m0 + row;
        float4 v = make_float4(0.f, 0.f, 0.f, 0.f);
        if (m < M) v = *(const float4*)(A + (size_t)m * lda + q * 4);
        int mw = row >> 5, mr = row & 31;
        int mi = mr >> 4, rr = mr & 15;
        int rowslot = rr >> 3, r = rr & 7;
        int kt = q >> 1, hi = q & 1;
        float* p = af + mw * 4160 + kt * 260 + mi * 128 + r * 16 + hi * 2 + rowslot;
        p[0]  = tf32r(v.x);   // c=0
        p[4]  = tf32r(v.y);   // c=1
        p[8]  = tf32r(v.z);   // c=2
        p[12] = tf32r(v.w);   // c=3
    }
    __syncthreads();

    int lane = tid & 31;
    int warp = tid >> 5;
    int mw = warp >> 1;          // 0..3
    int nw = warp & 1;           // 0..1
    int wm = mw * 32, wn = nw * 64;
    int r = lane >> 2, c = lane & 3;

    const uint4* wfv = (const uint4*)(wfrag + nw * 8192);
    const float* amy = af + mw * 4160 + lane * 4;

    float acc[2][8][4];
#pragma unroll
    for (int mi = 0; mi < 2; mi++)
#pragma unroll
        for (int ni = 0; ni < 8; ni++)
#pragma unroll
            for (int j = 0; j < 4; j++) acc[mi][ni][j] = 0.f;

#pragma unroll
    for (int kt = 0; kt < 16; kt++) {
        uint4 bf0 = wfv[(kt * 4 + 0) * 32 + lane];
        uint4 bf1 = wfv[(kt * 4 + 1) * 32 + lane];
        uint4 bf2 = wfv[(kt * 4 + 2) * 32 + lane];
        uint4 bf3 = wfv[(kt * 4 + 3) * 32 + lane];
        uint4 a0 = *(const uint4*)(amy + kt * 260);
        uint4 a1 = *(const uint4*)(amy + kt * 260 + 128);
        MMA_TF32(acc[0][0], a0.x, a0.y, a0.z, a0.w, bf0.x, bf0.y);
        MMA_TF32(acc[1][0], a1.x, a1.y, a1.z, a1.w, bf0.x, bf0.y);
        MMA_TF32(acc[0][1], a0.x, a0.y, a0.z, a0.w, bf0.z, bf0.w);
        MMA_TF32(acc[1][1], a1.x, a1.y, a1.z, a1.w, bf0.z, bf0.w);
        MMA_TF32(acc[0][2], a0.x, a0.y, a0.z, a0.w, bf1.x, bf1.y);
        MMA_TF32(acc[1][2], a1.x, a1.y, a1.z, a1.w, bf1.x, bf1.y);
        MMA_TF32(acc[0][3], a0.x, a0.y, a0.z, a0.w, bf1.z, bf1.w);
        MMA_TF32(acc[1][3], a1.x, a1.y, a1.z, a1.w, bf1.z, bf1.w);
        MMA_TF32(acc[0][4], a0.x, a0.y, a0.z, a0.w, bf2.x, bf2.y);
        MMA_TF32(acc[1][4], a1.x, a1.y, a1.z, a1.w, bf2.x, bf2.y);
        MMA_TF32(acc[0][5], a0.x, a0.y, a0.z, a0.w, bf2.z, bf2.w);
        MMA_TF32(acc[1][5], a1.x, a1.y, a1.z, a1.w, bf2.z, bf2.w);
        MMA_TF32(acc[0][6], a0.x, a0.y, a0.z, a0.w, bf3.x, bf3.y);
        MMA_TF32(acc[1][6], a1.x, a1.y, a1.z, a1.w, bf3.x, bf3.y);
        MMA_TF32(acc[0][7], a0.x, a0.y, a0.z, a0.w, bf3.z, bf3.w);
        MMA_TF32(acc[1][7], a1.x, a1.y, a1.z, a1.w, bf3.z, bf3.w);
    }

    // epilogue: bias + relu
#pragma unroll
    for (int mi = 0; mi < 2; mi++) {
        int row0 = m0 + wm + mi * 16 + r;
#pragma unroll
        for (int ni = 0; ni < 8; ni++) {
            int col = wn + ni * 8 + c * 2;
            float bx = __ldg(bias + col);
            float by = __ldg(bias + col + 1);
            if (row0 < M) {
                float2 o;
                o.x = fmaxf(acc[mi][ni][0] + bx, 0.f);
                o.y = fmaxf(acc[mi][ni][1] + by, 0.f);
                *(float2*)(C + (size_t)row0 * ldc + col) = o;
            }
            int row1 = row0 + 8;
            if (row1 < M) {
                float2 o;
                o.x = fmaxf(acc[mi][ni][2] + bx, 0.f);
                o.y = fmaxf(acc[mi][ni][3] + by, 0.f);
                *(float2*)(C + (size_t)row1 * ldc + col) = o;
            }
        }
    }
}

// ---------------- pooling ----------------
__global__ void k_bounds(const int* __restrict__ batch) {
    int i = blockIdx.x * blockDim.x + threadIdx.x;
    if (i >= NN) return;
    int b = batch[i];
    int pb = (i == 0) ? -1 : batch[i - 1];
    for (int g = pb + 1; g <= b; g++) d_gstart[g] = i;
    if (i == NN - 1)
        for (int g = b + 1; g <= NG; g++) d_gstart[g] = NN;
}

__global__ void k_pool() {
    int g = blockIdx.x;
    int t = threadIdx.x;
    int s = d_gstart[g], e = d_gstart[g + 1];
    float a0 = 0.f, a1 = 0.f, a2 = 0.f;
    for (int n = s; n < e; n++) {
        const float* row = d_xs + (size_t)n * 384;
        a0 += row[t];
        a1 += row[128 + t];
        a2 += row[256 + t];
    }
    d_g[g * 384 + t] = a0;
    d_g[g * 384 + 128 + t] = a1;
    d_g[g * 384 + 256 + t] = a2;
}

// ---------------- classifier ----------------
__global__ void __launch_bounds__(256)
k_clf(const float* __restrict__ w1, const float* __restrict__ b1,
      const float* __restrict__ w2, const float* __restrict__ b2,
      const float* __restrict__ gamma, const float* __restrict__ beta,
      const float* __restrict__ mean, const float* __restrict__ var,
      float* __restrict__ out) {
    __shared__ float sg[16 * 384];
    __shared__ float sz[16 * 256];
    int tid = threadIdx.x;
    int g0 = blockIdx.x * 16;
    for (int i = tid; i < 16 * 384; i += 256) sg[i] = d_g[g0 * 384 + i];
    __syncthreads();
    float acc[16];
#pragma unroll
    for (int gi = 0; gi < 16; gi++) acc[gi] = 0.f;
    for (int k = 0; k < 384; k++) {
        float w = __ldg(w1 + k * 256 + tid);
#pragma unroll
        for (int gi = 0; gi < 16; gi++) acc[gi] += sg[gi * 384 + k] * w;
    }
    float bb = __ldg(b1 + tid);
    float mu = __ldg(mean + tid);
    float iv = rsqrtf(__ldg(var + tid) + BN_EPS);
    float ga = __ldg(gamma + tid);
    float be = __ldg(beta + tid);
#pragma unroll
    for (int gi = 0; gi < 16; gi++) {
        float zv = acc[gi] + bb;
        zv = (zv - mu) * iv * ga + be;
        sz[gi * 256 + tid] = fmaxf(zv, 0.f);
    }
    __syncthreads();
    if (tid < 32) {
        int gi = tid >> 1, c = tid & 1;
        float s = __ldg(b2 + c);
        for (int k = 0; k < 256; k++) s += sz[gi * 256 + k] * __ldg(w2 + k * 2 + c);
        out[(g0 + gi) * 2 + c] = s;
    }
}

// ---------------- launch ----------------
extern "C" void kernel_launch(void* const* d_in, const int* in_sizes, int n_in,
                              void* d_out, int out_size) {
    const float* x   = (const float*)d_in[0];
    const int*   ei  = (const int*)d_in[1];
    const int*   bat = (const int*)d_in[2];
    const float* w1_0 = (const float*)d_in[3];
    const float* b1_0 = (const float*)d_in[4];
    const float* w2_0 = (const float*)d_in[5];
    const float* b2_0 = (const float*)d_in[6];
    const float* w1_1 = (const float*)d_in[7];
    const float* b1_1 = (const float*)d_in[8];
    const float* w2_1 = (const float*)d_in[9];
    const float* b2_1 = (const float*)d_in[10];
    const float* w1_2 = (const float*)d_in[11];
    const float* b1_2 = (const float*)d_in[12];
    const float* w2_2 = (const float*)d_in[13];
    const float* b2_2 = (const float*)d_in[14];
    const float* cw1 = (const float*)d_in[15];
    const float* cb1 = (const float*)d_in[16];
    const float* cw2 = (const float*)d_in[17];
    const float* cb2 = (const float*)d_in[18];
    const float* bng = (const float*)d_in[19];
    const float* bnb = (const float*)d_in[20];
    const float* bnm = (const float*)d_in[21];
    const float* bnv = (const float*)d_in[22];
    float* out = (float*)d_out;

    cudaFuncSetAttribute(k_gemm_tc, cudaFuncAttributeMaxDynamicSharedMemorySize,
                         GEMM_SMEM);

    static float* p_xs = nullptr;
    static float* p_A = nullptr;
    static float* p_z = nullptr;
    static float* p_wf = nullptr;
    if (!p_xs) {
        void* tmp;
        cudaGetSymbolAddress(&tmp, d_xs); p_xs = (float*)tmp;
        cudaGetSymbolAddress(&tmp, d_A);  p_A = (float*)tmp;
        cudaGetSymbolAddress(&tmp, d_z);  p_z = (float*)tmp;
        cudaGetSymbolAddress(&tmp, d_wf); p_wf = (float*)tmp;
    }

    int tb = 256;
    // W fragment tables (5 weight matrices used by the 5 tensor GEMMs)
    k_wfrag<<<(5 * 16384 + tb - 1) / tb, tb>>>(w2_0, w1_1, w2_1, w1_2, w2_2);
    // CSR build
    k_zero_deg<<<(NN + tb - 1) / tb, tb>>>();
    k_hist<<<(NE + tb - 1) / tb, tb>>>(ei);
    k_scan1<<<NSB, SCAN_B>>>();
    k_scan2<<<1, 256>>>();
    k_scan3<<<(NN + tb - 1) / tb, tb>>>();
    k_fill<<<(NE + tb - 1) / tb, tb>>>(ei);

    int gemm_grid = (NN + 127) / 128;
    int agg_grid = (NN * 32 + tb - 1) / tb;
    int g8 = (NN * 8 + tb - 1) / tb;

    // layer 0
    k_pad8<<<g8, tb>>>(x);
    k_agg8<<<g8, tb>>>();
    k_lin0<<<agg_grid, tb>>>(w1_0, b1_0);
    k_gemm_tc<<<gemm_grid, tb, GEMM_SMEM>>>(p_A, HID, p_wf + 0 * 16384, b2_0, p_xs + 0, 384, NN);
    // layer 1
    k_agg128<<<agg_grid, tb>>>(p_xs + 0, 384);
    k_gemm_tc<<<gemm_grid, tb, GEMM_SMEM>>>(p_z, HID, p_wf + 1 * 16384, b1_1, p_A, HID, NN);
    k_gemm_tc<<<gemm_grid, tb, GEMM_SMEM>>>(p_A, HID, p_wf + 2 * 16384, b2_1, p_xs + 128, 384, NN);
    // layer 2
    k_agg128<<<agg_grid, tb>>>(p_xs + 128, 384);
    k_gemm_tc<<<gemm_grid, tb, GEMM_SMEM>>>(p_z, HID, p_wf + 3 * 16384, b1_2, p_A, HID, NN);
    k_gemm_tc<<<gemm_grid, tb, GEMM_SMEM>>>(p_A, HID, p_wf + 4 * 16384, b2_2, p_xs + 256, 384, NN);
    // pool + classifier
    k_bounds<<<(NN + tb - 1) / tb, tb>>>(bat);
    k_pool<<<NG, 128>>>();
    k_clf<<<NG / 16, 256>>>(cw1, cb1, cw2, cb2, bng, bnb, bnm, bnv, out);
}

// round 9
// speedup vs baseline: 1.3670x; 1.0289x over previous
#include <cuda_runtime.h>
#include <cuda_fp16.h>
#include <cstdint>

#define NN 100000
#define NE 1600000
#define NG 1024
#define HID 128
#define BN_EPS 1e-5f

// ---------------- device scratch ----------------
__device__ int   d_deg[NN];
__device__ int   d_rowstart[NN + 1];
__device__ int   d_cursor[NN];
__device__ int   d_csr_src[NE];
#define SCAN_B 512
#define NSB ((NN + SCAN_B - 1) / SCAN_B)
__device__ int   d_blocksums[NSB];
__device__ int   d_blockoff[NSB];
__device__ float d_z7[NN * 8];
__device__ float d_A[NN * HID];
__device__ float d_z[NN * HID];      // also reused: first NN*8 = padded x8
__device__ float d_xs[NN * 3 * HID];
__device__ float d_g[NG * 3 * HID];
__device__ int   d_gstart[NG + 1];
// W fragment tables (fp16 packed): [5 layers][2 nw][8 kt][4 g][32 lane][4 u32]
__device__ unsigned int d_wf[5 * 2 * 8 * 4 * 32 * 4];

// ---------------- CSR build ----------------
__global__ void k_zero_deg() {
    int i = blockIdx.x * blockDim.x + threadIdx.x;
    if (i < NN) d_deg[i] = 0;
}

__global__ void k_hist(const int* __restrict__ ei) {
    int e = blockIdx.x * blockDim.x + threadIdx.x;
    if (e < NE) atomicAdd(&d_deg[ei[NE + e]], 1);
}

__global__ void k_scan1() {
    __shared__ int s[SCAN_B];
    int t = threadIdx.x;
    int i = blockIdx.x * SCAN_B + t;
    int v = (i < NN) ? d_deg[i] : 0;
    s[t] = v;
    __syncthreads();
    for (int off = 1; off < SCAN_B; off <<= 1) {
        int x = (t >= off) ? s[t - off] : 0;
        __syncthreads();
        s[t] += x;
        __syncthreads();
    }
    if (i < NN) d_rowstart[i] = s[t];
    if (t == SCAN_B - 1) d_blocksums[blockIdx.x] = s[t];
}

__global__ void k_scan2() {
    __shared__ int s[256];
    int t = threadIdx.x;
    int v = (t < NSB) ? d_blocksums[t] : 0;
    s[t] = v;
    __syncthreads();
    for (int off = 1; off < 256; off <<= 1) {
        int x = (t >= off) ? s[t - off] : 0;
        __syncthreads();
        s[t] += x;
        __syncthreads();
    }
    if (t < NSB) d_blockoff[t] = s[t] - v;
}

__global__ void k_scan3() {
    int i = blockIdx.x * blockDim.x + threadIdx.x;
    if (i < NN) {
        int incl = d_rowstart[i];
        int ex = incl - d_deg[i] + d_blockoff[i >> 9];
        d_rowstart[i] = ex;
        d_cursor[i] = ex;
    }
    if (i == 0) d_rowstart[NN] = NE;
}

__global__ void k_fill(const int* __restrict__ ei) {
    int e = blockIdx.x * blockDim.x + threadIdx.x;
    if (e < NE) {
        int dst = ei[NE + e];
        int pos = atomicAdd(&d_cursor[dst], 1);
        d_csr_src[pos] = ei[e];
    }
}

// ---------------- layer 0 ----------------
__global__ void k_pad8(const float* __restrict__ x) {
    int gt = blockIdx.x * blockDim.x + threadIdx.x;
    if (gt >= NN * 8) return;
    int n = gt >> 3, j = gt & 7;
    d_z[gt] = (j < 7) ? x[n * 7 + j] : 0.0f;
}

__global__ void k_agg8() {
    int gt = blockIdx.x * blockDim.x + threadIdx.x;
    if (gt >= NN * 8) return;
    int n = gt >> 3, j = gt & 7;
    float a = d_z[n * 8 + j];
    int s = d_rowstart[n], e = d_rowstart[n + 1];
    for (int i = s; i < e; i++) {
        int src = d_csr_src[i];
        a += __ldg(d_z + src * 8 + j);
    }
    d_z7[n * 8 + j] = a;
}

// lin0: A = relu(z7 @ w1_0 + b1_0), w1_0 is [7][128]
__global__ void k_lin0(const float* __restrict__ w1, const float* __restrict__ b1) {
    __shared__ float ws[7 * 128 + 128];
    int tid = threadIdx.x;
    for (int i = tid; i < 7 * 128 + 128; i += 256)
        ws[i] = (i < 7 * 128) ? w1[i] : b1[i - 7 * 128];
    __syncthreads();
    int gt = blockIdx.x * 256 + tid;
    int node = gt >> 5;
    int cg = gt & 31;
    if (node >= NN) return;
    float a[7];
#pragma unroll
    for (int j = 0; j < 7; j++) a[j] = d_z7[node * 8 + j];
    const float* bb = ws + 7 * 128;
    float4 acc = *(const float4*)(bb + cg * 4);
#pragma unroll
    for (int j = 0; j < 7; j++) {
        float4 w = *(const float4*)(ws + j * 128 + cg * 4);
        acc.x += a[j] * w.x;
        acc.y += a[j] * w.y;
        acc.z += a[j] * w.z;
        acc.w += a[j] * w.w;
    }
    acc.x = fmaxf(acc.x, 0.f); acc.y = fmaxf(acc.y, 0.f);
    acc.z = fmaxf(acc.z, 0.f); acc.w = fmaxf(acc.w, 0.f);
    *(float4*)(d_A + node * HID + cg * 4) = acc;
}

// ---------------- 128-dim aggregation ----------------
__global__ void k_agg128(const float* __restrict__ h, int ldh) {
    int gt = blockIdx.x * blockDim.x + threadIdx.x;
    int n = gt >> 5;
    int lane = gt & 31;
    if (n >= NN) return;
    float4 acc = *(const float4*)(h + (size_t)n * ldh + lane * 4);
    int s = d_rowstart[n], e = d_rowstart[n + 1];
    int i = s;
    for (; i + 1 < e; i += 2) {
        int s0 = d_csr_src[i];
        int s1 = d_csr_src[i + 1];
        float4 v0 = *(const float4*)(h + (size_t)s0 * ldh + lane * 4);
        float4 v1 = *(const float4*)(h + (size_t)s1 * ldh + lane * 4);
        acc.x += v0.x; acc.y += v0.y; acc.z += v0.z; acc.w += v0.w;
        acc.x += v1.x; acc.y += v1.y; acc.z += v1.z; acc.w += v1.w;
    }
    if (i < e) {
        int s0 = d_csr_src[i];
        float4 v0 = *(const float4*)(h + (size_t)s0 * ldh + lane * 4);
        acc.x += v0.x; acc.y += v0.y; acc.z += v0.z; acc.w += v0.w;
    }
    *(float4*)(d_z + n * HID + lane * 4) = acc;
}

// ---------------- fp16 pack helper ----------------
__device__ __forceinline__ unsigned int packh2(float a, float b) {
    __half2 h = __floats2half2_rn(a, b);
    return *reinterpret_cast<unsigned int*>(&h);
}

// ---------------- W fragment precompute (fp16, m16n8k16) ----------------
// d_wf layout: [layer][nw][kt(8)][g(4)][lane][4 u32]
// within uint4 (s=0..3): ni = 2g + (s>>1), breg = s&1
// value = packh2(W[klo][n], W[klo+1][n]); klo = kt*16 + 2c + 8*breg
// c = lane&3, r = lane>>2, n = nw*64 + ni*8 + r
__global__ void k_wfrag(const float* __restrict__ w0, const float* __restrict__ w1,
                        const float* __restrict__ w2, const float* __restrict__ w3,
                        const float* __restrict__ w4) {
    int idx = blockIdx.x * blockDim.x + threadIdx.x;
    if (idx >= 5 * 8192) return;
    int s = idx & 3;
    int lane = (idx >> 2) & 31;
    int g = (idx >> 7) & 3;
    int kt = (idx >> 9) & 7;
    int nw = (idx >> 12) & 1;
    int layer = idx >> 13;
    int ni = 2 * g + (s >> 1);
    int breg = s & 1;
    int r = lane >> 2, c = lane & 3;
    int klo = kt * 16 + 2 * c + 8 * breg;
    int n = nw * 64 + ni * 8 + r;
    const float* W = (layer == 0) ? w0 : (layer == 1) ? w1 : (layer == 2) ? w2
                   : (layer == 3) ? w3 : w4;
    d_wf[idx] = packh2(__ldg(W + klo * 128 + n), __ldg(W + (klo + 1) * 128 + n));
}

// ---------------- fp16 tensor-core GEMM (m16n8k16), fragment-order operands ----
// C[M,128] = relu(A[M,128] @ W + bias). BM=128. 8 warps = 4m x 2n, warp: 32x64.
// A smem (packed f16x2 u32): af[mw(4)][kt(8)][mi(2)][lane][4 regs] = 8192 u32 = 32 KB
#define GEMM_SMEM (8192 * 4)

#define MMA_F16(ac, a0, a1, a2, a3, b0, b1)                                    \
    asm volatile(                                                              \
        "mma.sync.aligned.m16n8k16.row.col.f32.f16.f16.f32 "                   \
        "{%0,%1,%2,%3}, {%4,%5,%6,%7}, {%8,%9}, {%0,%1,%2,%3};"                \
        : "+f"(ac[0]), "+f"(ac[1]), "+f"(ac[2]), "+f"(ac[3])                   \
        : "r"(a0), "r"(a1), "r"(a2), "r"(a3), "r"(b0), "r"(b1))

__global__ void __launch_bounds__(256, 2)
k_gemm_tc(const float* __restrict__ A, int lda,
          const unsigned int* __restrict__ wfrag, const float* __restrict__ bias,
          float* __restrict__ C, int ldc, int M) {
    extern __shared__ unsigned int af[];
    int tid = threadIdx.x;
    int m0 = blockIdx.x * 128;

    // stage A tile into fragment-order smem (fp16 packed)
#pragma unroll
    for (int it = tid; it < 128 * 32; it += 256) {
        int row = it >> 5, q = it & 31;
        int m = m0 + row;
        float4 v = make_float4(0.f, 0.f, 0.f, 0.f);
        if (m < M) v = *(const float4*)(A + (size_t)m * lda + q * 4);
        int mw = row >> 5, mr = row & 31;
        int mi = mr >> 4, rr = mr & 15;
        int jr = rr >> 3, r = rr & 7;
        int kt = q >> 2;
        int kk0 = (q & 3) * 4;                 // k offset within 16: 0,4,8,12
        int jk = (kk0 >= 8) ? 2 : 0;
        int c0 = (kk0 & 7) >> 1;               // 0 or 2
        int j = jr + jk;
        int base = ((mw * 8 + kt) * 2 + mi) * 128;
        af[base + (r * 4 + c0) * 4 + j]     = packh2(v.x, v.y);
        af[base + (r * 4 + c0 + 1) * 4 + j] = packh2(v.z, v.w);
    }
    __syncthreads();

    int lane = tid & 31;
    int warp = tid >> 5;
    int mw = warp >> 1;          // 0..3
    int nw = warp & 1;           // 0..1
    int wm = mw * 32, wn = nw * 64;
    int r = lane >> 2, c = lane & 3;

    const uint4* wfv = (const uint4*)(wfrag + nw * 4096);
    const uint4* av  = (const uint4*)af;

    float acc[2][8][4];
#pragma unroll
    for (int mi = 0; mi < 2; mi++)
#pragma unroll
        for (int ni = 0; ni < 8; ni++)
#pragma unroll
            for (int j = 0; j < 4; j++) acc[mi][ni][j] = 0.f;

#pragma unroll
    for (int kt = 0; kt < 8; kt++) {
        uint4 bf0 = wfv[(kt * 4 + 0) * 32 + lane];
        uint4 bf1 = wfv[(kt * 4 + 1) * 32 + lane];
        uint4 bf2 = wfv[(kt * 4 + 2) * 32 + lane];
        uint4 bf3 = wfv[(kt * 4 + 3) * 32 + lane];
        uint4 a0 = av[((mw * 8 + kt) * 2 + 0) * 32 + lane];
        uint4 a1 = av[((mw * 8 + kt) * 2 + 1) * 32 + lane];
        // uint4 bfg = {b0[ni=2g], b1[ni=2g], b0[ni=2g+1], b1[ni=2g+1]}
        MMA_F16(acc[0][0], a0.x, a0.y, a0.z, a0.w, bf0.x, bf0.y);
        MMA_F16(acc[1][0], a1.x, a1.y, a1.z, a1.w, bf0.x, bf0.y);
        MMA_F16(acc[0][1], a0.x, a0.y, a0.z, a0.w, bf0.z, bf0.w);
        MMA_F16(acc[1][1], a1.x, a1.y, a1.z, a1.w, bf0.z, bf0.w);
        MMA_F16(acc[0][2], a0.x, a0.y, a0.z, a0.w, bf1.x, bf1.y);
        MMA_F16(acc[1][2], a1.x, a1.y, a1.z, a1.w, bf1.x, bf1.y);
        MMA_F16(acc[0][3], a0.x, a0.y, a0.z, a0.w, bf1.z, bf1.w);
        MMA_F16(acc[1][3], a1.x, a1.y, a1.z, a1.w, bf1.z, bf1.w);
        MMA_F16(acc[0][4], a0.x, a0.y, a0.z, a0.w, bf2.x, bf2.y);
        MMA_F16(acc[1][4], a1.x, a1.y, a1.z, a1.w, bf2.x, bf2.y);
        MMA_F16(acc[0][5], a0.x, a0.y, a0.z, a0.w, bf2.z, bf2.w);
        MMA_F16(acc[1][5], a1.x, a1.y, a1.z, a1.w, bf2.z, bf2.w);
        MMA_F16(acc[0][6], a0.x, a0.y, a0.z, a0.w, bf3.x, bf3.y);
        MMA_F16(acc[1][6], a1.x, a1.y, a1.z, a1.w, bf3.x, bf3.y);
        MMA_F16(acc[0][7], a0.x, a0.y, a0.z, a0.w, bf3.z, bf3.w);
        MMA_F16(acc[1][7], a1.x, a1.y, a1.z, a1.w, bf3.z, bf3.w);
    }

    // epilogue: bias + relu
#pragma unroll
    for (int mi = 0; mi < 2; mi++) {
        int row0 = m0 + wm + mi * 16 + r;
#pragma unroll
        for (int ni = 0; ni < 8; ni++) {
            int col = wn + ni * 8 + c * 2;
            float bx = __ldg(bias + col);
            float by = __ldg(bias + col + 1);
            if (row0 < M) {
                float2 o;
                o.x = fmaxf(acc[mi][ni][0] + bx, 0.f);
                o.y = fmaxf(acc[mi][ni][1] + by, 0.f);
                *(float2*)(C + (size_t)row0 * ldc + col) = o;
            }
            int row1 = row0 + 8;
            if (row1 < M) {
                float2 o;
                o.x = fmaxf(acc[mi][ni][2] + bx, 0.f);
                o.y = fmaxf(acc[mi][ni][3] + by, 0.f);
                *(float2*)(C + (size_t)row1 * ldc + col) = o;
            }
        }
    }
}

// ---------------- pooling ----------------
__global__ void k_bounds(const int* __restrict__ batch) {
    int i = blockIdx.x * blockDim.x + threadIdx.x;
    if (i >= NN) return;
    int b = batch[i];
    int pb = (i == 0) ? -1 : batch[i - 1];
    for (int g = pb + 1; g <= b; g++) d_gstart[g] = i;
    if (i == NN - 1)
        for (int g = b + 1; g <= NG; g++) d_gstart[g] = NN;
}

__global__ void k_pool() {
    int g = blockIdx.x;
    int t = threadIdx.x;
    int s = d_gstart[g], e = d_gstart[g + 1];
    float a0 = 0.f, a1 = 0.f, a2 = 0.f;
    for (int n = s; n < e; n++) {
        const float* row = d_xs + (size_t)n * 384;
        a0 += row[t];
        a1 += row[128 + t];
        a2 += row[256 + t];
    }
    d_g[g * 384 + t] = a0;
    d_g[g * 384 + 128 + t] = a1;
    d_g[g * 384 + 256 + t] = a2;
}

// ---------------- classifier ----------------
__global__ void __launch_bounds__(256)
k_clf(const float* __restrict__ w1, const float* __restrict__ b1,
      const float* __restrict__ w2, const float* __restrict__ b2,
      const float* __restrict__ gamma, const float* __restrict__ beta,
      const float* __restrict__ mean, const float* __restrict__ var,
      float* __restrict__ out) {
    __shared__ float sg[16 * 384];
    __shared__ float sz[16 * 256];
    int tid = threadIdx.x;
    int g0 = blockIdx.x * 16;
    for (int i = tid; i < 16 * 384; i += 256) sg[i] = d_g[g0 * 384 + i];
    __syncthreads();
    float acc[16];
#pragma unroll
    for (int gi = 0; gi < 16; gi++) acc[gi] = 0.f;
    for (int k = 0; k < 384; k++) {
        float w = __ldg(w1 + k * 256 + tid);
#pragma unroll
        for (int gi = 0; gi < 16; gi++) acc[gi] += sg[gi * 384 + k] * w;
    }
    float bb = __ldg(b1 + tid);
    float mu = __ldg(mean + tid);
    float iv = rsqrtf(__ldg(var + tid) + BN_EPS);
    float ga = __ldg(gamma + tid);
    float be = __ldg(beta + tid);
#pragma unroll
    for (int gi = 0; gi < 16; gi++) {
        float zv = acc[gi] + bb;
        zv = (zv - mu) * iv * ga + be;
        sz[gi * 256 + tid] = fmaxf(zv, 0.f);
    }
    __syncthreads();
    if (tid < 32) {
        int gi = tid >> 1, c = tid & 1;
        float s = __ldg(b2 + c);
        for (int k = 0; k < 256; k++) s += sz[gi * 256 + k] * __ldg(w2 + k * 2 + c);
        out[(g0 + gi) * 2 + c] = s;
    }
}

// ---------------- launch ----------------
extern "C" void kernel_launch(void* const* d_in, const int* in_sizes, int n_in,
                              void* d_out, int out_size) {
    const float* x   = (const float*)d_in[0];
    const int*   ei  = (const int*)d_in[1];
    const int*   bat = (const int*)d_in[2];
    const float* w1_0 = (const float*)d_in[3];
    const float* b1_0 = (const float*)d_in[4];
    const float* w2_0 = (const float*)d_in[5];
    const float* b2_0 = (const float*)d_in[6];
    const float* w1_1 = (const float*)d_in[7];
    const float* b1_1 = (const float*)d_in[8];
    const float* w2_1 = (const float*)d_in[9];
    const float* b2_1 = (const float*)d_in[10];
    const float* w1_2 = (const float*)d_in[11];
    const float* b1_2 = (const float*)d_in[12];
    const float* w2_2 = (const float*)d_in[13];
    const float* b2_2 = (const float*)d_in[14];
    const float* cw1 = (const float*)d_in[15];
    const float* cb1 = (const float*)d_in[16];
    const float* cw2 = (const float*)d_in[17];
    const float* cb2 = (const float*)d_in[18];
    const float* bng = (const float*)d_in[19];
    const float* bnb = (const float*)d_in[20];
    const float* bnm = (const float*)d_in[21];
    const float* bnv = (const float*)d_in[22];
    float* out = (float*)d_out;

    cudaFuncSetAttribute(k_gemm_tc, cudaFuncAttributeMaxDynamicSharedMemorySize,
                         GEMM_SMEM);

    static float* p_xs = nullptr;
    static float* p_A = nullptr;
    static float* p_z = nullptr;
    static unsigned int* p_wf = nullptr;
    if (!p_xs) {
        void* tmp;
        cudaGetSymbolAddress(&tmp, d_xs); p_xs = (float*)tmp;
        cudaGetSymbolAddress(&tmp, d_A);  p_A = (float*)tmp;
        cudaGetSymbolAddress(&tmp, d_z);  p_z = (float*)tmp;
        cudaGetSymbolAddress(&tmp, d_wf); p_wf = (unsigned int*)tmp;
    }

    int tb = 256;
    // W fragment tables (5 weight matrices used by the 5 tensor GEMMs)
    k_wfrag<<<(5 * 8192 + tb - 1) / tb, tb>>>(w2_0, w1_1, w2_1, w1_2, w2_2);
    // CSR build
    k_zero_deg<<<(NN + tb - 1) / tb, tb>>>();
    k_hist<<<(NE + tb - 1) / tb, tb>>>(ei);
    k_scan1<<<NSB, SCAN_B>>>();
    k_scan2<<<1, 256>>>();
    k_scan3<<<(NN + tb - 1) / tb, tb>>>();
    k_fill<<<(NE + tb - 1) / tb, tb>>>(ei);

    int gemm_grid = (NN + 127) / 128;
    int agg_grid = (NN * 32 + tb - 1) / tb;
    int g8 = (NN * 8 + tb - 1) / tb;

    // layer 0
    k_pad8<<<g8, tb>>>(x);
    k_agg8<<<g8, tb>>>();
    k_lin0<<<agg_grid, tb>>>(w1_0, b1_0);
    k_gemm_tc<<<gemm_grid, tb, GEMM_SMEM>>>(p_A, HID, p_wf + 0 * 8192, b2_0, p_xs + 0, 384, NN);
    // layer 1
    k_agg128<<<agg_grid, tb>>>(p_xs + 0, 384);
    k_gemm_tc<<<gemm_grid, tb, GEMM_SMEM>>>(p_z, HID, p_wf + 1 * 8192, b1_1, p_A, HID, NN);
    k_gemm_tc<<<gemm_grid, tb, GEMM_SMEM>>>(p_A, HID, p_wf + 2 * 8192, b2_1, p_xs + 128, 384, NN);
    // layer 2
    k_agg128<<<agg_grid, tb>>>(p_xs + 128, 384);
    k_gemm_tc<<<gemm_grid, tb, GEMM_SMEM>>>(p_z, HID, p_wf + 3 * 8192, b1_2, p_A, HID, NN);
    k_gemm_tc<<<gemm_grid, tb, GEMM_SMEM>>>(p_A, HID, p_wf + 4 * 8192, b2_2, p_xs + 256, 384, NN);
    // pool + classifier
    k_bounds<<<(NN + tb - 1) / tb, tb>>>(bat);
    k_pool<<<NG, 128>>>();
    k_clf<<<NG / 16, 256>>>(cw1, cb1, cw2, cb2, bng, bnb, bnm, bnv, out);
}

// round 14
// speedup vs baseline: 1.6919x; 1.2376x over previous
#include <cuda_runtime.h>
#include <cuda_fp16.h>
#include <cstdint>

#define NN 100000
#define NE 1600000
#define NG 1024
#define HID 128
#define BN_EPS 1e-5f

// ---------------- device scratch ----------------
__device__ int   d_deg[NN];
__device__ int   d_rowstart[NN + 1];
__device__ int   d_cursor[NN];
__device__ int   d_csr_src[NE];
#define SCAN_B 512
#define NSB ((NN + SCAN_B - 1) / SCAN_B)
__device__ int   d_blocksums[NSB];
__device__ int   d_blockoff[NSB];
__device__ float d_z[NN * 8];                       // padded x8
__device__ float d_xs[NN * 3 * HID];                // jk-cat fp32 (pool input)
__device__ __align__(16) unsigned int d_zh[NN * 64];   // fp16 z (GEMM A input)
__device__ __align__(16) unsigned int d_xsh[NN * 64];  // fp16 layer output (gather src)
__device__ float d_g[NG * 3 * HID];
__device__ int   d_gstart[NG + 1];
// W fragment tables (fp16 packed u32):
// T0 w1_0 (KT=1):  off 0,     size 1024
// T1 w2_0 (KT=8):  off 1024,  size 8192
// T2 w1_1: 9216 | T3 w2_1: 17408 | T4 w1_2: 25600 | T5 w2_2: 33792
__device__ __align__(16) unsigned int d_wf[41984];

// ---------------- CSR build ----------------
__global__ void k_zero_deg() {
    int i = blockIdx.x * blockDim.x + threadIdx.x;
    if (i < NN) d_deg[i] = 0;
}

__global__ void k_hist(const int* __restrict__ ei) {
    int e = blockIdx.x * blockDim.x + threadIdx.x;
    if (e < NE) atomicAdd(&d_deg[ei[NE + e]], 1);
}

__global__ void k_scan1() {
    __shared__ int s[SCAN_B];
    int t = threadIdx.x;
    int i = blockIdx.x * SCAN_B + t;
    int v = (i < NN) ? d_deg[i] : 0;
    s[t] = v;
    __syncthreads();
    for (int off = 1; off < SCAN_B; off <<= 1) {
        int x = (t >= off) ? s[t - off] : 0;
        __syncthreads();
        s[t] += x;
        __syncthreads();
    }
    if (i < NN) d_rowstart[i] = s[t];
    if (t == SCAN_B - 1) d_blocksums[blockIdx.x] = s[t];
}

__global__ void k_scan2() {
    __shared__ int s[256];
    int t = threadIdx.x;
    int v = (t < NSB) ? d_blocksums[t] : 0;
    s[t] = v;
    __syncthreads();
    for (int off = 1; off < 256; off <<= 1) {
        int x = (t >= off) ? s[t - off] : 0;
        __syncthreads();
        s[t] += x;
        __syncthreads();
    }
    if (t < NSB) d_blockoff[t] = s[t] - v;
}

__global__ void k_scan3() {
    int i = blockIdx.x * blockDim.x + threadIdx.x;
    if (i < NN) {
        int incl = d_rowstart[i];
        int ex = incl - d_deg[i] + d_blockoff[i >> 9];
        d_rowstart[i] = ex;
        d_cursor[i] = ex;
    }
    if (i == 0) d_rowstart[NN] = NE;
}

__global__ void k_fill(const int* __restrict__ ei) {
    int e = blockIdx.x * blockDim.x + threadIdx.x;
    if (e < NE) {
        int dst = ei[NE + e];
        int pos = atomicAdd(&d_cursor[dst], 1);
        d_csr_src[pos] = ei[e];
    }
}

// ---------------- fp16 helpers ----------------
__device__ __forceinline__ unsigned int packh2(float a, float b) {
    __half2 h = __floats2half2_rn(a, b);
    return *reinterpret_cast<unsigned int*>(&h);
}
__device__ __forceinline__ float2 uh2f2(unsigned int u) {
    __half2 h = *reinterpret_cast<__half2*>(&u);
    return __half22float2(h);
}

// ---------------- layer 0 prep ----------------
__global__ void k_pad8(const float* __restrict__ x) {
    int gt = blockIdx.x * blockDim.x + threadIdx.x;
    if (gt >= NN * 8) return;
    int n = gt >> 3, j = gt & 7;
    d_z[gt] = (j < 7) ? x[n * 7 + j] : 0.0f;
}

// z7 = x8[n] + sum x8[src]; 4 lanes/node, output packed fp16 padded to K=16
__global__ void k_agg8h() {
    int gt = blockIdx.x * blockDim.x + threadIdx.x;
    if (gt >= NN * 4) return;
    int n = gt >> 2, j = gt & 3;
    float2 a = *(const float2*)(d_z + n * 8 + 2 * j);
    int s = d_rowstart[n], e = d_rowstart[n + 1];
    for (int i = s; i < e; i++) {
        int src = d_csr_src[i];
        float2 v = __ldg((const float2*)(d_z + src * 8 + 2 * j));
        a.x += v.x; a.y += v.y;
    }
    d_zh[n * 8 + j] = packh2(a.x, a.y);
    d_zh[n * 8 + 4 + j] = 0u;
}

// ---------------- fp16 128-dim aggregation: z = h + sum h[src] -------------
__global__ void k_aggh() {
    int gt = blockIdx.x * blockDim.x + threadIdx.x;
    int n = gt >> 5, lane = gt & 31;
    if (n >= NN) return;
    const uint2* hp = (const uint2*)d_xsh;
    uint2 sv = hp[(size_t)n * 32 + lane];
    float2 f0 = uh2f2(sv.x), f1 = uh2f2(sv.y);
    float ax = f0.x, ay = f0.y, az = f1.x, aw = f1.y;
    int s = d_rowstart[n], e = d_rowstart[n + 1];
    int i = s;
    for (; i + 1 < e; i += 2) {
        int s0 = d_csr_src[i];
        int s1 = d_csr_src[i + 1];
        uint2 v0 = __ldg(&hp[(size_t)s0 * 32 + lane]);
        uint2 v1 = __ldg(&hp[(size_t)s1 * 32 + lane]);
        float2 g0 = uh2f2(v0.x), g1 = uh2f2(v0.y);
        float2 g2 = uh2f2(v1.x), g3 = uh2f2(v1.y);
        ax += g0.x + g2.x; ay += g0.y + g2.y;
        az += g1.x + g3.x; aw += g1.y + g3.y;
    }
    if (i < e) {
        int s0 = d_csr_src[i];
        uint2 v0 = __ldg(&hp[(size_t)s0 * 32 + lane]);
        float2 g0 = uh2f2(v0.x), g1 = uh2f2(v0.y);
        ax += g0.x; ay += g0.y; az += g1.x; aw += g1.y;
    }
    d_zh[(size_t)n * 64 + lane * 2]     = packh2(ax, ay);
    d_zh[(size_t)n * 64 + lane * 2 + 1] = packh2(az, aw);
}

// ---------------- W fragment precompute (fp16, m16n8k16) ----------------
__device__ __forceinline__ void wfrag_fill(const float* W, unsigned int* dst,
                                           int local, int KT, int fan) {
    int per_nw = KT * 512;
    int nw = local / per_nw;
    int rem = local % per_nw;
    int kt = rem >> 9;
    int low = rem & 511;
    int s = low & 3;
    int lane = (low >> 2) & 31;
    int g = low >> 7;
    int ni = 2 * g + (s >> 1);
    int breg = s & 1;
    int r = lane >> 2, c = lane & 3;
    int klo = kt * 16 + 2 * c + 8 * breg;
    int n = nw * 64 + ni * 8 + r;
    float v0 = (klo < fan)     ? __ldg(W + klo * 128 + n)       : 0.f;
    float v1 = (klo + 1 < fan) ? __ldg(W + (klo + 1) * 128 + n) : 0.f;
    dst[local] = packh2(v0, v1);
}

__global__ void k_wfrag(const float* __restrict__ w10, const float* __restrict__ w20,
                        const float* __restrict__ w11, const float* __restrict__ w21,
                        const float* __restrict__ w12, const float* __restrict__ w22) {
    int idx = blockIdx.x * blockDim.x + threadIdx.x;
    if (idx >= 41984) return;
    if (idx < 1024) { wfrag_fill(w10, d_wf, idx, 1, 7); return; }
    int t = (idx - 1024) >> 13;           // 0..4
    int local = (idx - 1024) & 8191;
    const float* W = (t == 0) ? w20 : (t == 1) ? w11 : (t == 2) ? w21
                   : (t == 3) ? w12 : w22;
    wfrag_fill(W, d_wf + 1024 + t * 8192, local, 8, 128);
}

// ---------------- fused layer kernel ----------------
// xs_col = relu( relu(Z@W1 + b1) @ W2 + b2 ), Z fp16 [M, KT1*16], hidden in smem.
#define MMA_F16(ac, a0, a1, a2, a3, b0, b1)                                    \
    asm volatile(                                                              \
        "mma.sync.aligned.m16n8k16.row.col.f32.f16.f16.f32 "                   \
        "{%0,%1,%2,%3}, {%4,%5,%6,%7}, {%8,%9}, {%0,%1,%2,%3};"                \
        : "+f"(ac[0]), "+f"(ac[1]), "+f"(ac[2]), "+f"(ac[3])                   \
        : "r"(a0), "r"(a1), "r"(a2), "r"(a3), "r"(b0), "r"(b1))

template <int KT1>
__global__ void __launch_bounds__(256, 2)
k_layer(const unsigned int* __restrict__ zsrc, int zld,
        const unsigned int* __restrict__ wf1, const float* __restrict__ b1,
        const unsigned int* __restrict__ wf2, const float* __restrict__ b2,
        float* __restrict__ xs_out, unsigned int* __restrict__ xsh_out, int M) {
    __shared__ __align__(16) unsigned int af[8192];  // A1 fragments, then H fragments
    int tid = threadIdx.x;
    int m0 = blockIdx.x * 128;

    // ---- stage Z (fp16 packed row-major) into A-fragment smem ----
    // row = KT1*8 u32 pairs = KT1*2 uint4; q indexes uint4 within row.
    const int QN = KT1 * 2;
#pragma unroll
    for (int it = tid; it < 128 * QN; it += 256) {
        int row = it / QN, q = it % QN;
        int m = m0 + row;
        uint4 v = make_uint4(0u, 0u, 0u, 0u);
        if (m < M) v = *(const uint4*)(zsrc + (size_t)m * zld + q * 4);
        int mw = row >> 5, mr = row & 31;
        int mi = mr >> 4, rr = mr & 15;
        int jr = rr >> 3, r = rr & 7;
        unsigned int vals[4] = {v.x, v.y, v.z, v.w};
#pragma unroll
        for (int i = 0; i < 4; i++) {
            int p = q * 4 + i;                    // u32-pair index 0..KT1*8-1
            int kt = p >> 3, pp = p & 7;
            int c = pp & 3, jk = (pp & 4) ? 2 : 0;
            af[((mw * KT1 + kt) * 2 + mi) * 128 + (r * 4 + c) * 4 + jr + jk] = vals[i];
        }
    }
    __syncthreads();

    int lane = tid & 31;
    int warp = tid >> 5;
    int mw = warp >> 1;          // 0..3
    int nw = warp & 1;           // 0..1
    int r = lane >> 2, c = lane & 3;

    float acc[2][8][4];
#pragma unroll
    for (int mi = 0; mi < 2; mi++)
#pragma unroll
        for (int ni = 0; ni < 8; ni++)
#pragma unroll
            for (int j = 0; j < 4; j++) acc[mi][ni][j] = 0.f;

    // ---- GEMM1 ----
    {
        const uint4* wfv = (const uint4*)(wf1 + nw * (KT1 * 512));
        const uint4* av = (const uint4*)af;
#pragma unroll
        for (int kt = 0; kt < KT1; kt++) {
            uint4 bf0 = wfv[(kt * 4 + 0) * 32 + lane];
            uint4 bf1 = wfv[(kt * 4 + 1) * 32 + lane];
            uint4 bf2 = wfv[(kt * 4 + 2) * 32 + lane];
            uint4 bf3 = wfv[(kt * 4 + 3) * 32 + lane];
            uint4 a0 = av[((mw * KT1 + kt) * 2 + 0) * 32 + lane];
            uint4 a1 = av[((mw * KT1 + kt) * 2 + 1) * 32 + lane];
            MMA_F16(acc[0][0], a0.x, a0.y, a0.z, a0.w, bf0.x, bf0.y);
            MMA_F16(acc[1][0], a1.x, a1.y, a1.z, a1.w, bf0.x, bf0.y);
            MMA_F16(acc[0][1], a0.x, a0.y, a0.z, a0.w, bf0.z, bf0.w);
            MMA_F16(acc[1][1], a1.x, a1.y, a1.z, a1.w, bf0.z, bf0.w);
            MMA_F16(acc[0][2], a0.x, a0.y, a0.z, a0.w, bf1.x, bf1.y);
            MMA_F16(acc[1][2], a1.x, a1.y, a1.z, a1.w, bf1.x, bf1.y);
            MMA_F16(acc[0][3], a0.x, a0.y, a0.z, a0.w, bf1.z, bf1.w);
            MMA_F16(acc[1][3], a1.x, a1.y, a1.z, a1.w, bf1.z, bf1.w);
            MMA_F16(acc[0][4], a0.x, a0.y, a0.z, a0.w, bf2.x, bf2.y);
            MMA_F16(acc[1][4], a1.x, a1.y, a1.z, a1.w, bf2.x, bf2.y);
            MMA_F16(acc[0][5], a0.x, a0.y, a0.z, a0.w, bf2.z, bf2.w);
            MMA_F16(acc[1][5], a1.x, a1.y, a1.z, a1.w, bf2.z, bf2.w);
            MMA_F16(acc[0][6], a0.x, a0.y, a0.z, a0.w, bf3.x, bf3.y);
            MMA_F16(acc[1][6], a1.x, a1.y, a1.z, a1.w, bf3.x, bf3.y);
            MMA_F16(acc[0][7], a0.x, a0.y, a0.z, a0.w, bf3.z, bf3.w);
            MMA_F16(acc[1][7], a1.x, a1.y, a1.z, a1.w, bf3.z, bf3.w);
        }
    }
    __syncthreads();   // done reading A1 fragments

    // ---- epilogue1: relu(acc+b1) -> H fragments in af (fp16 packed) ----
#pragma unroll
    for (int mi = 0; mi < 2; mi++) {
#pragma unroll
        for (int ni = 0; ni < 8; ni++) {
            int col = nw * 64 + ni * 8 + 2 * c;
            float bx = __ldg(b1 + col);
            float by = __ldg(b1 + col + 1);
            unsigned int lo = packh2(fmaxf(acc[mi][ni][0] + bx, 0.f),
                                     fmaxf(acc[mi][ni][1] + by, 0.f));
            unsigned int hi = packh2(fmaxf(acc[mi][ni][2] + bx, 0.f),
                                     fmaxf(acc[mi][ni][3] + by, 0.f));
            int P = nw * 32 + ni * 4 + c;              // u32-pair 0..63
            int kt2 = P >> 3, pp = P & 7;
            int c2 = pp & 3, jk = (pp & 4) ? 2 : 0;
            int base = ((mw * 8 + kt2) * 2 + mi) * 128 + (r * 4 + c2) * 4 + jk;
            af[base]     = lo;   // row wm+mi*16+r      (jr=0)
            af[base + 1] = hi;   // row wm+mi*16+r+8    (jr=1)
            acc[mi][ni][0] = 0.f; acc[mi][ni][1] = 0.f;
            acc[mi][ni][2] = 0.f; acc[mi][ni][3] = 0.f;
        }
    }
    __syncthreads();

    // ---- GEMM2 (KT=8) ----
    {
        const uint4* wfv = (const uint4*)(wf2 + nw * 4096);
        const uint4* av = (const uint4*)af;
#pragma unroll
        for (int kt = 0; kt < 8; kt++) {
            uint4 bf0 = wfv[(kt * 4 + 0) * 32 + lane];
            uint4 bf1 = wfv[(kt * 4 + 1) * 32 + lane];
            uint4 bf2 = wfv[(kt * 4 + 2) * 32 + lane];
            uint4 bf3 = wfv[(kt * 4 + 3) * 32 + lane];
            uint4 a0 = av[((mw * 8 + kt) * 2 + 0) * 32 + lane];
            uint4 a1 = av[((mw * 8 + kt) * 2 + 1) * 32 + lane];
            MMA_F16(acc[0][0], a0.x, a0.y, a0.z, a0.w, bf0.x, bf0.y);
            MMA_F16(acc[1][0], a1.x, a1.y, a1.z, a1.w, bf0.x, bf0.y);
            MMA_F16(acc[0][1], a0.x, a0.y, a0.z, a0.w, bf0.z, bf0.w);
            MMA_F16(acc[1][1], a1.x, a1.y, a1.z, a1.w, bf0.z, bf0.w);
            MMA_F16(acc[0][2], a0.x, a0.y, a0.z, a0.w, bf1.x, bf1.y);
            MMA_F16(acc[1][2], a1.x, a1.y, a1.z, a1.w, bf1.x, bf1.y);
            MMA_F16(acc[0][3], a0.x, a0.y, a0.z, a0.w, bf1.z, bf1.w);
            MMA_F16(acc[1][3], a1.x, a1.y, a1.z, a1.w, bf1.z, bf1.w);
            MMA_F16(acc[0][4], a0.x, a0.y, a0.z, a0.w, bf2.x, bf2.y);
            MMA_F16(acc[1][4], a1.x, a1.y, a1.z, a1.w, bf2.x, bf2.y);
            MMA_F16(acc[0][5], a0.x, a0.y, a0.z, a0.w, bf2.z, bf2.w);
            MMA_F16(acc[1][5], a1.x, a1.y, a1.z, a1.w, bf2.z, bf2.w);
            MMA_F16(acc[0][6], a0.x, a0.y, a0.z, a0.w, bf3.x, bf3.y);
            MMA_F16(acc[1][6], a1.x, a1.y, a1.z, a1.w, bf3.x, bf3.y);
            MMA_F16(acc[0][7], a0.x, a0.y, a0.z, a0.w, bf3.z, bf3.w);
            MMA_F16(acc[1][7], a1.x, a1.y, a1.z, a1.w, bf3.z, bf3.w);
        }
    }

    // ---- epilogue2: relu(acc+b2) -> xs fp32 (stride 384) + optional fp16 copy
#pragma unroll
    for (int mi = 0; mi < 2; mi++) {
        int row0 = m0 + mw * 32 + mi * 16 + r;
        int row1 = row0 + 8;
#pragma unroll
        for (int ni = 0; ni < 8; ni++) {
            int col = nw * 64 + ni * 8 + 2 * c;
            float bx = __ldg(b2 + col);
            float by = __ldg(b2 + col + 1);
            float o0 = fmaxf(acc[mi][ni][0] + bx, 0.f);
            float o1 = fmaxf(acc[mi][ni][1] + by, 0.f);
            float o2 = fmaxf(acc[mi][ni][2] + bx, 0.f);
            float o3 = fmaxf(acc[mi][ni][3] + by, 0.f);
            int P = nw * 32 + ni * 4 + c;
            if (row0 < M) {
                *(float2*)(xs_out + (size_t)row0 * 384 + col) = make_float2(o0, o1);
                if (xsh_out) xsh_out[(size_t)row0 * 64 + P] = packh2(o0, o1);
            }
            if (row1 < M) {
                *(float2*)(xs_out + (size_t)row1 * 384 + col) = make_float2(o2, o3);
                if (xsh_out) xsh_out[(size_t)row1 * 64 + P] = packh2(o2, o3);
            }
        }
    }
}

// ---------------- pooling ----------------
__global__ void k_bounds(const int* __restrict__ batch) {
    int i = blockIdx.x * blockDim.x + threadIdx.x;
    if (i >= NN) return;
    int b = batch[i];
    int pb = (i == 0) ? -1 : batch[i - 1];
    for (int g = pb + 1; g <= b; g++) d_gstart[g] = i;
    if (i == NN - 1)
        for (int g = b + 1; g <= NG; g++) d_gstart[g] = NN;
}

__global__ void k_pool() {
    int g = blockIdx.x;
    int t = threadIdx.x;
    int s = d_gstart[g], e = d_gstart[g + 1];
    float a0 = 0.f, a1 = 0.f, a2 = 0.f;
    for (int n = s; n < e; n++) {
        const float* row = d_xs + (size_t)n * 384;
        a0 += row[t];
        a1 += row[128 + t];
        a2 += row[256 + t];
    }
    d_g[g * 384 + t] = a0;
    d_g[g * 384 + 128 + t] = a1;
    d_g[g * 384 + 256 + t] = a2;
}

// ---------------- classifier ----------------
__global__ void __launch_bounds__(256)
k_clf(const float* __restrict__ w1, const float* __restrict__ b1,
      const float* __restrict__ w2, const float* __restrict__ b2,
      const float* __restrict__ gamma, const float* __restrict__ beta,
      const float* __restrict__ mean, const float* __restrict__ var,
      float* __restrict__ out) {
    __shared__ float sg[16 * 384];
    __shared__ float sz[16 * 256];
    int tid = threadIdx.x;
    int g0 = blockIdx.x * 16;
    for (int i = tid; i < 16 * 384; i += 256) sg[i] = d_g[g0 * 384 + i];
    __syncthreads();
    float acc[16];
#pragma unroll
    for (int gi = 0; gi < 16; gi++) acc[gi] = 0.f;
    for (int k = 0; k < 384; k++) {
        float w = __ldg(w1 + k * 256 + tid);
#pragma unroll
        for (int gi = 0; gi < 16; gi++) acc[gi] += sg[gi * 384 + k] * w;
    }
    float bb = __ldg(b1 + tid);
    float mu = __ldg(mean + tid);
    float iv = rsqrtf(__ldg(var + tid) + BN_EPS);
    float ga = __ldg(gamma + tid);
    float be = __ldg(beta + tid);
#pragma unroll
    for (int gi = 0; gi < 16; gi++) {
        float zv = acc[gi] + bb;
        zv = (zv - mu) * iv * ga + be;
        sz[gi * 256 + tid] = fmaxf(zv, 0.f);
    }
    __syncthreads();
    if (tid < 32) {
        int gi = tid >> 1, c = tid & 1;
        float s = __ldg(b2 + c);
        for (int k = 0; k < 256; k++) s += sz[gi * 256 + k] * __ldg(w2 + k * 2 + c);
        out[(g0 + gi) * 2 + c] = s;
    }
}

// ---------------- launch ----------------
extern "C" void kernel_launch(void* const* d_in, const int* in_sizes, int n_in,
                              void* d_out, int out_size) {
    const float* x   = (const float*)d_in[0];
    const int*   ei  = (const int*)d_in[1];
    const int*   bat = (const int*)d_in[2];
    const float* w1_0 = (const float*)d_in[3];
    const float* b1_0 = (const float*)d_in[4];
    const float* w2_0 = (const float*)d_in[5];
    const float* b2_0 = (const float*)d_in[6];
    const float* w1_1 = (const float*)d_in[7];
    const float* b1_1 = (const float*)d_in[8];
    const float* w2_1 = (const float*)d_in[9];
    const float* b2_1 = (const float*)d_in[10];
    const float* w1_2 = (const float*)d_in[11];
    const float* b1_2 = (const float*)d_in[12];
    const float* w2_2 = (const float*)d_in[13];
    const float* b2_2 = (const float*)d_in[14];
    const float* cw1 = (const float*)d_in[15];
    const float* cb1 = (const float*)d_in[16];
    const float* cw2 = (const float*)d_in[17];
    const float* cb2 = (const float*)d_in[18];
    const float* bng = (const float*)d_in[19];
    const float* bnb = (const float*)d_in[20];
    const float* bnm = (const float*)d_in[21];
    const float* bnv = (const float*)d_in[22];
    float* out = (float*)d_out;

    static float* p_xs = nullptr;
    static unsigned int* p_wf = nullptr;
    static unsigned int* p_zh = nullptr;
    static unsigned int* p_xsh = nullptr;
    if (!p_xs) {
        void* tmp;
        cudaGetSymbolAddress(&tmp, d_xs);  p_xs = (float*)tmp;
        cudaGetSymbolAddress(&tmp, d_wf);  p_wf = (unsigned int*)tmp;
        cudaGetSymbolAddress(&tmp, d_zh);  p_zh = (unsigned int*)tmp;
        cudaGetSymbolAddress(&tmp, d_xsh); p_xsh = (unsigned int*)tmp;
    }

    int tb = 256;
    // W fragment tables
    k_wfrag<<<(41984 + tb - 1) / tb, tb>>>(w1_0, w2_0, w1_1, w2_1, w1_2, w2_2);
    // CSR build
    k_zero_deg<<<(NN + tb - 1) / tb, tb>>>();
    k_hist<<<(NE + tb - 1) / tb, tb>>>(ei);
    k_scan1<<<NSB, SCAN_B>>>();
    k_scan2<<<1, 256>>>();
    k_scan3<<<(NN + tb - 1) / tb, tb>>>();
    k_fill<<<(NE + tb - 1) / tb, tb>>>(ei);

    int gemm_grid = (NN + 127) / 128;
    int agg_grid = (NN * 32 + tb - 1) / tb;

    // layer 0
    k_pad8<<<(NN * 8 + tb - 1) / tb, tb>>>(x);
    k_agg8h<<<(NN * 4 + tb - 1) / tb, tb>>>();
    k_layer<1><<<gemm_grid, tb>>>(p_zh, 8, p_wf + 0, b1_0, p_wf + 1024, b2_0,
                                  p_xs + 0, p_xsh, NN);
    // layer 1
    k_aggh<<<agg_grid, tb>>>();
    k_layer<8><<<gemm_grid, tb>>>(p_zh, 64, p_wf + 9216, b1_1, p_wf + 17408, b2_1,
                                  p_xs + 128, p_xsh, NN);
    // layer 2
    k_aggh<<<agg_grid, tb>>>();
    k_layer<8><<<gemm_grid, tb>>>(p_zh, 64, p_wf + 25600, b1_2, p_wf + 33792, b2_2,
                                  p_xs + 256, nullptr, NN);
    // pool + classifier
    k_bounds<<<(NN + tb - 1) / tb, tb>>>(bat);
    k_pool<<<NG, 128>>>();
    k_clf<<<NG / 16, 256>>>(cw1, cb1, cw2, cb2, bng, bnb, bnm, bnv, out);
}

// round 15
// speedup vs baseline: 1.9179x; 1.1336x over previous
#include <cuda_runtime.h>
#include <cuda_fp16.h>
#include <cstdint>

#define NN 100000
#define NE 1600000
#define NG 1024
#define HID 128
#define BN_EPS 1e-5f

// ---------------- device scratch ----------------
__device__ int   d_deg[NN];
__device__ int   d_rowstart[NN + 1];
__device__ int   d_cursor[NN];
__device__ int   d_csr_src[NE];
#define SCAN_B 512
#define NSB ((NN + SCAN_B - 1) / SCAN_B)
__device__ int   d_blocksums[NSB];
__device__ int   d_blockoff[NSB];
__device__ float d_z[NN * 8];                       // padded x8
__device__ __align__(16) unsigned int d_zh[NN * 64];    // fp16 z (GEMM A input)
__device__ __align__(16) unsigned int d_xsh0[NN * 64];  // fp16 layer outputs
__device__ __align__(16) unsigned int d_xsh1[NN * 64];
__device__ __align__(16) unsigned int d_xsh2[NN * 64];
__device__ float d_g[NG * 3 * HID];
__device__ int   d_gstart[NG + 1];
// W fragment tables (fp16 packed u32):
// T0 w1_0 (KT=1):  off 0,     size 1024
// T1 w2_0 (KT=8):  off 1024,  size 8192
// T2 w1_1: 9216 | T3 w2_1: 17408 | T4 w1_2: 25600 | T5 w2_2: 33792
__device__ __align__(16) unsigned int d_wf[41984];

// ---------------- CSR build ----------------
__global__ void k_zero_deg() {
    int i = blockIdx.x * blockDim.x + threadIdx.x;
    if (i < NN) d_deg[i] = 0;
}

__global__ void k_hist(const int* __restrict__ ei) {
    int e = blockIdx.x * blockDim.x + threadIdx.x;
    if (e < NE) atomicAdd(&d_deg[ei[NE + e]], 1);
}

__global__ void k_scan1() {
    __shared__ int s[SCAN_B];
    int t = threadIdx.x;
    int i = blockIdx.x * SCAN_B + t;
    int v = (i < NN) ? d_deg[i] : 0;
    s[t] = v;
    __syncthreads();
    for (int off = 1; off < SCAN_B; off <<= 1) {
        int x = (t >= off) ? s[t - off] : 0;
        __syncthreads();
        s[t] += x;
        __syncthreads();
    }
    if (i < NN) d_rowstart[i] = s[t];
    if (t == SCAN_B - 1) d_blocksums[blockIdx.x] = s[t];
}

__global__ void k_scan2() {
    __shared__ int s[256];
    int t = threadIdx.x;
    int v = (t < NSB) ? d_blocksums[t] : 0;
    s[t] = v;
    __syncthreads();
    for (int off = 1; off < 256; off <<= 1) {
        int x = (t >= off) ? s[t - off] : 0;
        __syncthreads();
        s[t] += x;
        __syncthreads();
    }
    if (t < NSB) d_blockoff[t] = s[t] - v;
}

__global__ void k_scan3() {
    int i = blockIdx.x * blockDim.x + threadIdx.x;
    if (i < NN) {
        int incl = d_rowstart[i];
        int ex = incl - d_deg[i] + d_blockoff[i >> 9];
        d_rowstart[i] = ex;
        d_cursor[i] = ex;
    }
    if (i == 0) d_rowstart[NN] = NE;
}

__global__ void k_fill(const int* __restrict__ ei) {
    int e = blockIdx.x * blockDim.x + threadIdx.x;
    if (e < NE) {
        int dst = ei[NE + e];
        int pos = atomicAdd(&d_cursor[dst], 1);
        d_csr_src[pos] = ei[e];
    }
}

// ---------------- fp16 helpers ----------------
__device__ __forceinline__ unsigned int packh2(float a, float b) {
    __half2 h = __floats2half2_rn(a, b);
    return *reinterpret_cast<unsigned int*>(&h);
}
__device__ __forceinline__ float2 uh2f2(unsigned int u) {
    __half2 h = *reinterpret_cast<__half2*>(&u);
    return __half22float2(h);
}

// ---------------- layer 0 prep ----------------
__global__ void k_pad8(const float* __restrict__ x) {
    int gt = blockIdx.x * blockDim.x + threadIdx.x;
    if (gt >= NN * 8) return;
    int n = gt >> 3, j = gt & 7;
    d_z[gt] = (j < 7) ? x[n * 7 + j] : 0.0f;
}

// z7 = x8[n] + sum x8[src]; 4 lanes/node, output packed fp16 padded to K=16
__global__ void k_agg8h() {
    int gt = blockIdx.x * blockDim.x + threadIdx.x;
    if (gt >= NN * 4) return;
    int n = gt >> 2, j = gt & 3;
    float2 a = *(const float2*)(d_z + n * 8 + 2 * j);
    int s = d_rowstart[n], e = d_rowstart[n + 1];
    for (int i = s; i < e; i++) {
        int src = d_csr_src[i];
        float2 v = __ldg((const float2*)(d_z + src * 8 + 2 * j));
        a.x += v.x; a.y += v.y;
    }
    d_zh[n * 8 + j] = packh2(a.x, a.y);
    d_zh[n * 8 + 4 + j] = 0u;
}

// ---------------- fp16 128-dim aggregation: z = h + sum h[src] -------------
__global__ void k_aggh(const unsigned int* __restrict__ hsrc) {
    int gt = blockIdx.x * blockDim.x + threadIdx.x;
    int n = gt >> 5, lane = gt & 31;
    if (n >= NN) return;
    const uint2* hp = (const uint2*)hsrc;
    uint2 sv = hp[(size_t)n * 32 + lane];
    float2 f0 = uh2f2(sv.x), f1 = uh2f2(sv.y);
    float ax = f0.x, ay = f0.y, az = f1.x, aw = f1.y;
    int s = d_rowstart[n], e = d_rowstart[n + 1];
    int i = s;
    for (; i + 1 < e; i += 2) {
        int s0 = d_csr_src[i];
        int s1 = d_csr_src[i + 1];
        uint2 v0 = __ldg(&hp[(size_t)s0 * 32 + lane]);
        uint2 v1 = __ldg(&hp[(size_t)s1 * 32 + lane]);
        float2 g0 = uh2f2(v0.x), g1 = uh2f2(v0.y);
        float2 g2 = uh2f2(v1.x), g3 = uh2f2(v1.y);
        ax += g0.x + g2.x; ay += g0.y + g2.y;
        az += g1.x + g3.x; aw += g1.y + g3.y;
    }
    if (i < e) {
        int s0 = d_csr_src[i];
        uint2 v0 = __ldg(&hp[(size_t)s0 * 32 + lane]);
        float2 g0 = uh2f2(v0.x), g1 = uh2f2(v0.y);
        ax += g0.x; ay += g0.y; az += g1.x; aw += g1.y;
    }
    d_zh[(size_t)n * 64 + lane * 2]     = packh2(ax, ay);
    d_zh[(size_t)n * 64 + lane * 2 + 1] = packh2(az, aw);
}

// ---------------- W fragment precompute (fp16, m16n8k16) ----------------
__device__ __forceinline__ void wfrag_fill(const float* W, unsigned int* dst,
                                           int local, int KT, int fan) {
    int per_nw = KT * 512;
    int nw = local / per_nw;
    int rem = local % per_nw;
    int kt = rem >> 9;
    int low = rem & 511;
    int s = low & 3;
    int lane = (low >> 2) & 31;
    int g = low >> 7;
    int ni = 2 * g + (s >> 1);
    int breg = s & 1;
    int r = lane >> 2, c = lane & 3;
    int klo = kt * 16 + 2 * c + 8 * breg;
    int n = nw * 64 + ni * 8 + r;
    float v0 = (klo < fan)     ? __ldg(W + klo * 128 + n)       : 0.f;
    float v1 = (klo + 1 < fan) ? __ldg(W + (klo + 1) * 128 + n) : 0.f;
    dst[local] = packh2(v0, v1);
}

__global__ void k_wfrag(const float* __restrict__ w10, const float* __restrict__ w20,
                        const float* __restrict__ w11, const float* __restrict__ w21,
                        const float* __restrict__ w12, const float* __restrict__ w22) {
    int idx = blockIdx.x * blockDim.x + threadIdx.x;
    if (idx >= 41984) return;
    if (idx < 1024) { wfrag_fill(w10, d_wf, idx, 1, 7); return; }
    int t = (idx - 1024) >> 13;           // 0..4
    int local = (idx - 1024) & 8191;
    const float* W = (t == 0) ? w20 : (t == 1) ? w11 : (t == 2) ? w21
                   : (t == 3) ? w12 : w22;
    wfrag_fill(W, d_wf + 1024 + t * 8192, local, 8, 128);
}

// ---------------- fused layer kernel ----------------
// out = relu( relu(Z@W1 + b1) @ W2 + b2 ), Z fp16 [M, KT1*16], hidden in smem.
// Output: fp16 only (u32 index P holds cols 2P, 2P+1).
#define MMA_F16(ac, a0, a1, a2, a3, b0, b1)                                    \
    asm volatile(                                                              \
        "mma.sync.aligned.m16n8k16.row.col.f32.f16.f16.f32 "                   \
        "{%0,%1,%2,%3}, {%4,%5,%6,%7}, {%8,%9}, {%0,%1,%2,%3};"                \
        : "+f"(ac[0]), "+f"(ac[1]), "+f"(ac[2]), "+f"(ac[3])                   \
        : "r"(a0), "r"(a1), "r"(a2), "r"(a3), "r"(b0), "r"(b1))

template <int KT1>
__global__ void __launch_bounds__(256, 2)
k_layer(const unsigned int* __restrict__ zsrc, int zld,
        const unsigned int* __restrict__ wf1, const float* __restrict__ b1,
        const unsigned int* __restrict__ wf2, const float* __restrict__ b2,
        unsigned int* __restrict__ xsh_out, int M) {
    __shared__ __align__(16) unsigned int af[8192];  // A1 fragments, then H fragments
    int tid = threadIdx.x;
    int m0 = blockIdx.x * 128;

    // ---- stage Z (fp16 packed row-major) into A-fragment smem ----
    const int QN = KT1 * 2;
#pragma unroll
    for (int it = tid; it < 128 * QN; it += 256) {
        int row = it / QN, q = it % QN;
        int m = m0 + row;
        uint4 v = make_uint4(0u, 0u, 0u, 0u);
        if (m < M) v = *(const uint4*)(zsrc + (size_t)m * zld + q * 4);
        int mw = row >> 5, mr = row & 31;
        int mi = mr >> 4, rr = mr & 15;
        int jr = rr >> 3, r = rr & 7;
        unsigned int vals[4] = {v.x, v.y, v.z, v.w};
#pragma unroll
        for (int i = 0; i < 4; i++) {
            int p = q * 4 + i;                    // u32-pair index 0..KT1*8-1
            int kt = p >> 3, pp = p & 7;
            int c = pp & 3, jk = (pp & 4) ? 2 : 0;
            af[((mw * KT1 + kt) * 2 + mi) * 128 + (r * 4 + c) * 4 + jr + jk] = vals[i];
        }
    }
    __syncthreads();

    int lane = tid & 31;
    int warp = tid >> 5;
    int mw = warp >> 1;          // 0..3
    int nw = warp & 1;           // 0..1
    int r = lane >> 2, c = lane & 3;

    float acc[2][8][4];
#pragma unroll
    for (int mi = 0; mi < 2; mi++)
#pragma unroll
        for (int ni = 0; ni < 8; ni++)
#pragma unroll
            for (int j = 0; j < 4; j++) acc[mi][ni][j] = 0.f;

    // ---- GEMM1 ----
    {
        const uint4* wfv = (const uint4*)(wf1 + nw * (KT1 * 512));
        const uint4* av = (const uint4*)af;
#pragma unroll
        for (int kt = 0; kt < KT1; kt++) {
            uint4 bf0 = wfv[(kt * 4 + 0) * 32 + lane];
            uint4 bf1 = wfv[(kt * 4 + 1) * 32 + lane];
            uint4 bf2 = wfv[(kt * 4 + 2) * 32 + lane];
            uint4 bf3 = wfv[(kt * 4 + 3) * 32 + lane];
            uint4 a0 = av[((mw * KT1 + kt) * 2 + 0) * 32 + lane];
            uint4 a1 = av[((mw * KT1 + kt) * 2 + 1) * 32 + lane];
            MMA_F16(acc[0][0], a0.x, a0.y, a0.z, a0.w, bf0.x, bf0.y);
            MMA_F16(acc[1][0], a1.x, a1.y, a1.z, a1.w, bf0.x, bf0.y);
            MMA_F16(acc[0][1], a0.x, a0.y, a0.z, a0.w, bf0.z, bf0.w);
            MMA_F16(acc[1][1], a1.x, a1.y, a1.z, a1.w, bf0.z, bf0.w);
            MMA_F16(acc[0][2], a0.x, a0.y, a0.z, a0.w, bf1.x, bf1.y);
            MMA_F16(acc[1][2], a1.x, a1.y, a1.z, a1.w, bf1.x, bf1.y);
            MMA_F16(acc[0][3], a0.x, a0.y, a0.z, a0.w, bf1.z, bf1.w);
            MMA_F16(acc[1][3], a1.x, a1.y, a1.z, a1.w, bf1.z, bf1.w);
            MMA_F16(acc[0][4], a0.x, a0.y, a0.z, a0.w, bf2.x, bf2.y);
            MMA_F16(acc[1][4], a1.x, a1.y, a1.z, a1.w, bf2.x, bf2.y);
            MMA_F16(acc[0][5], a0.x, a0.y, a0.z, a0.w, bf2.z, bf2.w);
            MMA_F16(acc[1][5], a1.x, a1.y, a1.z, a1.w, bf2.z, bf2.w);
            MMA_F16(acc[0][6], a0.x, a0.y, a0.z, a0.w, bf3.x, bf3.y);
            MMA_F16(acc[1][6], a1.x, a1.y, a1.z, a1.w, bf3.x, bf3.y);
            MMA_F16(acc[0][7], a0.x, a0.y, a0.z, a0.w, bf3.z, bf3.w);
            MMA_F16(acc[1][7], a1.x, a1.y, a1.z, a1.w, bf3.z, bf3.w);
        }
    }
    __syncthreads();   // done reading A1 fragments

    // ---- epilogue1: relu(acc+b1) -> H fragments in af (fp16 packed) ----
#pragma unroll
    for (int mi = 0; mi < 2; mi++) {
#pragma unroll
        for (int ni = 0; ni < 8; ni++) {
            int col = nw * 64 + ni * 8 + 2 * c;
            float bx = __ldg(b1 + col);
            float by = __ldg(b1 + col + 1);
            unsigned int lo = packh2(fmaxf(acc[mi][ni][0] + bx, 0.f),
                                     fmaxf(acc[mi][ni][1] + by, 0.f));
            unsigned int hi = packh2(fmaxf(acc[mi][ni][2] + bx, 0.f),
                                     fmaxf(acc[mi][ni][3] + by, 0.f));
            int P = nw * 32 + ni * 4 + c;              // u32-pair 0..63
            int kt2 = P >> 3, pp = P & 7;
            int c2 = pp & 3, jk = (pp & 4) ? 2 : 0;
            int base = ((mw * 8 + kt2) * 2 + mi) * 128 + (r * 4 + c2) * 4 + jk;
            af[base]     = lo;   // row wm+mi*16+r      (jr=0)
            af[base + 1] = hi;   // row wm+mi*16+r+8    (jr=1)
            acc[mi][ni][0] = 0.f; acc[mi][ni][1] = 0.f;
            acc[mi][ni][2] = 0.f; acc[mi][ni][3] = 0.f;
        }
    }
    __syncthreads();

    // ---- GEMM2 (KT=8) ----
    {
        const uint4* wfv = (const uint4*)(wf2 + nw * 4096);
        const uint4* av = (const uint4*)af;
#pragma unroll
        for (int kt = 0; kt < 8; kt++) {
            uint4 bf0 = wfv[(kt * 4 + 0) * 32 + lane];
            uint4 bf1 = wfv[(kt * 4 + 1) * 32 + lane];
            uint4 bf2 = wfv[(kt * 4 + 2) * 32 + lane];
            uint4 bf3 = wfv[(kt * 4 + 3) * 32 + lane];
            uint4 a0 = av[((mw * 8 + kt) * 2 + 0) * 32 + lane];
            uint4 a1 = av[((mw * 8 + kt) * 2 + 1) * 32 + lane];
            MMA_F16(acc[0][0], a0.x, a0.y, a0.z, a0.w, bf0.x, bf0.y);
            MMA_F16(acc[1][0], a1.x, a1.y, a1.z, a1.w, bf0.x, bf0.y);
            MMA_F16(acc[0][1], a0.x, a0.y, a0.z, a0.w, bf0.z, bf0.w);
            MMA_F16(acc[1][1], a1.x, a1.y, a1.z, a1.w, bf0.z, bf0.w);
            MMA_F16(acc[0][2], a0.x, a0.y, a0.z, a0.w, bf1.x, bf1.y);
            MMA_F16(acc[1][2], a1.x, a1.y, a1.z, a1.w, bf1.x, bf1.y);
            MMA_F16(acc[0][3], a0.x, a0.y, a0.z, a0.w, bf1.z, bf1.w);
            MMA_F16(acc[1][3], a1.x, a1.y, a1.z, a1.w, bf1.z, bf1.w);
            MMA_F16(acc[0][4], a0.x, a0.y, a0.z, a0.w, bf2.x, bf2.y);
            MMA_F16(acc[1][4], a1.x, a1.y, a1.z, a1.w, bf2.x, bf2.y);
            MMA_F16(acc[0][5], a0.x, a0.y, a0.z, a0.w, bf2.z, bf2.w);
            MMA_F16(acc[1][5], a1.x, a1.y, a1.z, a1.w, bf2.z, bf2.w);
            MMA_F16(acc[0][6], a0.x, a0.y, a0.z, a0.w, bf3.x, bf3.y);
            MMA_F16(acc[1][6], a1.x, a1.y, a1.z, a1.w, bf3.x, bf3.y);
            MMA_F16(acc[0][7], a0.x, a0.y, a0.z, a0.w, bf3.z, bf3.w);
            MMA_F16(acc[1][7], a1.x, a1.y, a1.z, a1.w, bf3.z, bf3.w);
        }
    }

    // ---- epilogue2: relu(acc+b2) -> fp16 output only ----
#pragma unroll
    for (int mi = 0; mi < 2; mi++) {
        int row0 = m0 + mw * 32 + mi * 16 + r;
        int row1 = row0 + 8;
#pragma unroll
        for (int ni = 0; ni < 8; ni++) {
            int col = nw * 64 + ni * 8 + 2 * c;
            float bx = __ldg(b2 + col);
            float by = __ldg(b2 + col + 1);
            int P = nw * 32 + ni * 4 + c;
            if (row0 < M)
                xsh_out[(size_t)row0 * 64 + P] =
                    packh2(fmaxf(acc[mi][ni][0] + bx, 0.f),
                           fmaxf(acc[mi][ni][1] + by, 0.f));
            if (row1 < M)
                xsh_out[(size_t)row1 * 64 + P] =
                    packh2(fmaxf(acc[mi][ni][2] + bx, 0.f),
                           fmaxf(acc[mi][ni][3] + by, 0.f));
        }
    }
}

// ---------------- pooling ----------------
__global__ void k_bounds(const int* __restrict__ batch) {
    int i = blockIdx.x * blockDim.x + threadIdx.x;
    if (i >= NN) return;
    int b = batch[i];
    int pb = (i == 0) ? -1 : batch[i - 1];
    for (int g = pb + 1; g <= b; g++) d_gstart[g] = i;
    if (i == NN - 1)
        for (int g = b + 1; g <= NG; g++) d_gstart[g] = NN;
}

// one block (192 threads) per graph; thread t = buf*64 + j handles u32 j of buffer buf
__global__ void __launch_bounds__(192)
k_pool() {
    int g = blockIdx.x;
    int t = threadIdx.x;
    int buf = t >> 6, j = t & 63;
    const unsigned int* src = (buf == 0) ? d_xsh0 : (buf == 1) ? d_xsh1 : d_xsh2;
    int s = d_gstart[g], e = d_gstart[g + 1];
    float a0 = 0.f, a1 = 0.f;
    for (int n = s; n < e; n++) {
        float2 f = uh2f2(__ldg(src + (size_t)n * 64 + j));
        a0 += f.x; a1 += f.y;
    }
    d_g[g * 384 + buf * 128 + 2 * j]     = a0;
    d_g[g * 384 + buf * 128 + 2 * j + 1] = a1;
}

// ---------------- classifier ----------------
__global__ void __launch_bounds__(256)
k_clf(const float* __restrict__ w1, const float* __restrict__ b1,
      const float* __restrict__ w2, const float* __restrict__ b2,
      const float* __restrict__ gamma, const float* __restrict__ beta,
      const float* __restrict__ mean, const float* __restrict__ var,
      float* __restrict__ out) {
    __shared__ float sg[16 * 384];
    __shared__ float sz[16 * 256];
    int tid = threadIdx.x;
    int g0 = blockIdx.x * 16;
    for (int i = tid; i < 16 * 384; i += 256) sg[i] = d_g[g0 * 384 + i];
    __syncthreads();
    float acc[16];
#pragma unroll
    for (int gi = 0; gi < 16; gi++) acc[gi] = 0.f;
    for (int k = 0; k < 384; k++) {
        float w = __ldg(w1 + k * 256 + tid);
#pragma unroll
        for (int gi = 0; gi < 16; gi++) acc[gi] += sg[gi * 384 + k] * w;
    }
    float bb = __ldg(b1 + tid);
    float mu = __ldg(mean + tid);
    float iv = rsqrtf(__ldg(var + tid) + BN_EPS);
    float ga = __ldg(gamma + tid);
    float be = __ldg(beta + tid);
#pragma unroll
    for (int gi = 0; gi < 16; gi++) {
        float zv = acc[gi] + bb;
        zv = (zv - mu) * iv * ga + be;
        sz[gi * 256 + tid] = fmaxf(zv, 0.f);
    }
    __syncthreads();
    if (tid < 32) {
        int gi = tid >> 1, c = tid & 1;
        float s = __ldg(b2 + c);
        for (int k = 0; k < 256; k++) s += sz[gi * 256 + k] * __ldg(w2 + k * 2 + c);
        out[(g0 + gi) * 2 + c] = s;
    }
}

// ---------------- launch ----------------
extern "C" void kernel_launch(void* const* d_in, const int* in_sizes, int n_in,
                              void* d_out, int out_size) {
    const float* x   = (const float*)d_in[0];
    const int*   ei  = (const int*)d_in[1];
    const int*   bat = (const int*)d_in[2];
    const float* w1_0 = (const float*)d_in[3];
    const float* b1_0 = (const float*)d_in[4];
    const float* w2_0 = (const float*)d_in[5];
    const float* b2_0 = (const float*)d_in[6];
    const float* w1_1 = (const float*)d_in[7];
    const float* b1_1 = (const float*)d_in[8];
    const float* w2_1 = (const float*)d_in[9];
    const float* b2_1 = (const float*)d_in[10];
    const float* w1_2 = (const float*)d_in[11];
    const float* b1_2 = (const float*)d_in[12];
    const float* w2_2 = (const float*)d_in[13];
    const float* b2_2 = (const float*)d_in[14];
    const float* cw1 = (const float*)d_in[15];
    const float* cb1 = (const float*)d_in[16];
    const float* cw2 = (const float*)d_in[17];
    const float* cb2 = (const float*)d_in[18];
    const float* bng = (const float*)d_in[19];
    const float* bnb = (const float*)d_in[20];
    const float* bnm = (const float*)d_in[21];
    const float* bnv = (const float*)d_in[22];
    float* out = (float*)d_out;

    static unsigned int* p_wf = nullptr;
    static unsigned int* p_zh = nullptr;
    static unsigned int* p_x0 = nullptr;
    static unsigned int* p_x1 = nullptr;
    static unsigned int* p_x2 = nullptr;
    if (!p_wf) {
        void* tmp;
        cudaGetSymbolAddress(&tmp, d_wf);   p_wf = (unsigned int*)tmp;
        cudaGetSymbolAddress(&tmp, d_zh);   p_zh = (unsigned int*)tmp;
        cudaGetSymbolAddress(&tmp, d_xsh0); p_x0 = (unsigned int*)tmp;
        cudaGetSymbolAddress(&tmp, d_xsh1); p_x1 = (unsigned int*)tmp;
        cudaGetSymbolAddress(&tmp, d_xsh2); p_x2 = (unsigned int*)tmp;
    }

    int tb = 256;
    // W fragment tables
    k_wfrag<<<(41984 + tb - 1) / tb, tb>>>(w1_0, w2_0, w1_1, w2_1, w1_2, w2_2);
    // CSR build
    k_zero_deg<<<(NN + tb - 1) / tb, tb>>>();
    k_hist<<<(NE + tb - 1) / tb, tb>>>(ei);
    k_scan1<<<NSB, SCAN_B>>>();
    k_scan2<<<1, 256>>>();
    k_scan3<<<(NN + tb - 1) / tb, tb>>>();
    k_fill<<<(NE + tb - 1) / tb, tb>>>(ei);

    int gemm_grid = (NN + 127) / 128;
    int agg_grid = (NN * 32 + tb - 1) / tb;

    // layer 0
    k_pad8<<<(NN * 8 + tb - 1) / tb, tb>>>(x);
    k_agg8h<<<(NN * 4 + tb - 1) / tb, tb>>>();
    k_layer<1><<<gemm_grid, tb>>>(p_zh, 8, p_wf + 0, b1_0, p_wf + 1024, b2_0,
                                  p_x0, NN);
    // layer 1
    k_aggh<<<agg_grid, tb>>>(p_x0);
    k_layer<8><<<gemm_grid, tb>>>(p_zh, 64, p_wf + 9216, b1_1, p_wf + 17408, b2_1,
                                  p_x1, NN);
    // layer 2
    k_aggh<<<agg_grid, tb>>>(p_x1);
    k_layer<8><<<gemm_grid, tb>>>(p_zh, 64, p_wf + 25600, b1_2, p_wf + 33792, b2_2,
                                  p_x2, NN);
    // pool + classifier
    k_bounds<<<(NN + tb - 1) / tb, tb>>>(bat);
    k_pool<<<NG, 192>>>();
    k_clf<<<NG / 16, 256>>>(cw1, cb1, cw2, cb2, bng, bnb, bnm, bnv, out);
}